// round 4
// baseline (speedup 1.0000x reference)
#include <cuda_runtime.h>
#include <math.h>
#include <stdint.h>

#define Bx   128
#define Nx   197
#define Cx   768
#define Hx   12
#define Dx   64
#define NROWS 25216      /* Bx*Nx */
#define LEFT 138
#define CMPL 58
#define NM   139
#define M2   17792       /* Bx*NM */
#define FF   3072

/* ---------------- device scratch (no allocations allowed) ---------------- */
__device__ float g_xn [NROWS*Cx];
__device__ float g_qkv[NROWS*3*Cx];
__device__ float g_ao [NROWS*Cx];
__device__ float g_x1 [NROWS*Cx];
__device__ float g_clsh[Bx*Hx*196];
__device__ float g_cls[Bx*196];
__device__ int   g_idx[Bx*LEFT];
__device__ int   g_cmp[Bx*CMPL];
__device__ float g_NT[Bx*64*Cx];
__device__ float g_XO[Bx*144*Cx];
__device__ float g_nrm[Bx*LEFT];
__device__ float g_D[Bx*64*144];
__device__ int   g_node[Bx*CMPL];
__device__ float g_xm [M2*Cx];
__device__ float g_xn2[M2*Cx];
__device__ float g_h1 [M2*FF];

/* ---------------- packed f32x2 helpers (Blackwell FFMA2) ---------------- */
__device__ __forceinline__ unsigned long long ffma2(unsigned long long a,
                                                    unsigned long long b,
                                                    unsigned long long c)
{
    unsigned long long d;
    asm("fma.rn.f32x2 %0, %1, %2, %3;" : "=l"(d) : "l"(a), "l"(b), "l"(c));
    return d;
}
__device__ __forceinline__ unsigned long long bcast2(float b)
{
    unsigned long long d;
    asm("mov.b64 %0, {%1, %1};" : "=l"(d) : "f"(b));
    return d;
}
__device__ __forceinline__ float2 unpk2(unsigned long long v)
{
    float2 r;
    asm("mov.b64 {%0, %1}, %2;" : "=f"(r.x), "=f"(r.y) : "l"(v));
    return r;
}

/* ---------------- LayerNorm: one block per row, 256 thr, C=768 ---------------- */
__global__ __launch_bounds__(256) void ln_kernel(const float* __restrict__ x,
                                                 const float* __restrict__ w,
                                                 const float* __restrict__ bb,
                                                 float* __restrict__ y)
{
    int row = blockIdx.x;
    const float* xr = x + (size_t)row * Cx;
    float* yr = y + (size_t)row * Cx;
    int t = threadIdx.x;
    float v0 = xr[t], v1 = xr[t+256], v2 = xr[t+512];
    float s = v0+v1+v2;
    float q = v0*v0 + v1*v1 + v2*v2;
    __shared__ float sred[16];
    #pragma unroll
    for (int o=16;o;o>>=1){ s += __shfl_xor_sync(0xffffffffu,s,o); q += __shfl_xor_sync(0xffffffffu,q,o); }
    if ((t&31)==0){ sred[t>>5] = s; sred[8+(t>>5)] = q; }
    __syncthreads();
    s = 0.f; q = 0.f;
    #pragma unroll
    for (int i=0;i<8;i++){ s += sred[i]; q += sred[8+i]; }
    float mean = s * (1.0f/768.0f);
    float var  = q * (1.0f/768.0f) - mean*mean;
    float rstd = rsqrtf(var + 1e-5f);
    yr[t]     = (v0-mean)*rstd*w[t]     + bb[t];
    yr[t+256] = (v1-mean)*rstd*w[t+256] + bb[t+256];
    yr[t+512] = (v2-mean)*rstd*w[t+512] + bb[t+512];
}

/* ---------- SGEMM2: 128x128x8, 256 thr, 8x8/thread, packed FFMA2 ----------
   Bit-exact fp32 (fma.rn.f32x2 == two IEEE fmaf). Conflict-free fragment
   loads: per-thread cols {tx*4..+3} and {64+tx*4..+3}; m-pairs packed free
   from m-contiguous As rows.
   EPI: 0 = none, 1 = +bias, 2 = +bias+residual, 3 = +bias+exact GELU       */
template<int EPI>
__global__ __launch_bounds__(256) void sgemm2(const float* __restrict__ A,
                                              const float* __restrict__ B,
                                              const float* __restrict__ bias,
                                              const float* __restrict__ res,
                                              float* __restrict__ C,
                                              int M, int N, int K)
{
    __shared__ float As[8][128];
    __shared__ float Bs[8][128];
    int tid = threadIdx.x;
    int bm = blockIdx.y << 7, bn = blockIdx.x << 7;
    const float* Ap = A + (size_t)(bm + (tid>>1))*K + ((tid&1)<<2);
    const float* Bp = B + (size_t)(tid>>5)*N + bn + ((tid&31)<<2);
    int tx = tid & 15, ty = tid >> 4;
    int arow = tid>>1, ac = (tid&1)<<2;
    int brow = tid>>5, bc = (tid&31)<<2;

    unsigned long long acc[4][8];
    #pragma unroll
    for (int i=0;i<4;i++)
        #pragma unroll
        for (int j=0;j<8;j++) acc[i][j] = 0ull;

    for (int k0=0;k0<K;k0+=8){
        float4 av = *(const float4*)Ap; Ap += 8;
        float4 bv = *(const float4*)Bp; Bp += (size_t)8*N;
        As[ac+0][arow]=av.x; As[ac+1][arow]=av.y; As[ac+2][arow]=av.z; As[ac+3][arow]=av.w;
        *(float4*)&Bs[brow][bc] = bv;
        __syncthreads();
        #pragma unroll
        for (int kk=0;kk<8;kk++){
            ulonglong2 a01 = *(const ulonglong2*)&As[kk][ty<<3];
            ulonglong2 a23 = *(const ulonglong2*)&As[kk][(ty<<3)+4];
            float4 b0 = *(const float4*)&Bs[kk][tx<<2];
            float4 b1 = *(const float4*)&Bs[kk][64 + (tx<<2)];
            unsigned long long aa[4];
            aa[0]=a01.x; aa[1]=a01.y; aa[2]=a23.x; aa[3]=a23.y;
            unsigned long long bd[8];
            bd[0]=bcast2(b0.x); bd[1]=bcast2(b0.y); bd[2]=bcast2(b0.z); bd[3]=bcast2(b0.w);
            bd[4]=bcast2(b1.x); bd[5]=bcast2(b1.y); bd[6]=bcast2(b1.z); bd[7]=bcast2(b1.w);
            #pragma unroll
            for (int i=0;i<4;i++)
                #pragma unroll
                for (int j=0;j<8;j++)
                    acc[i][j] = ffma2(aa[i], bd[j], acc[i][j]);
        }
        __syncthreads();
    }

    /* epilogue: thread rows bm+ty*8+{0..7} (pairs), cols bn+{tx*4, 64+tx*4} */
    #pragma unroll
    for (int i=0;i<4;i++){
        int r0 = bm + (ty<<3) + (i<<1);
        float vals[2][8];
        #pragma unroll
        for (int j=0;j<8;j++){
            float2 u = unpk2(acc[i][j]);
            vals[0][j] = u.x;            /* even row */
            vals[1][j] = u.y;            /* odd  row */
        }
        #pragma unroll
        for (int rr=0;rr<2;rr++){
            int row = r0 + rr;
            #pragma unroll
            for (int half=0;half<2;half++){
                int col = bn + (half<<6) + (tx<<2);
                size_t off = (size_t)row*N + col;
                float4 v;
                v.x = vals[rr][half*4+0];
                v.y = vals[rr][half*4+1];
                v.z = vals[rr][half*4+2];
                v.w = vals[rr][half*4+3];
                if (EPI >= 1){
                    float4 bb4 = *(const float4*)&bias[col];
                    v.x += bb4.x; v.y += bb4.y; v.z += bb4.z; v.w += bb4.w;
                }
                if (EPI == 2){
                    float4 r4 = *(const float4*)&res[off];
                    v.x += r4.x; v.y += r4.y; v.z += r4.z; v.w += r4.w;
                }
                if (EPI == 3){
                    v.x = 0.5f*v.x*(1.0f + erff(v.x*0.70710678118654752f));
                    v.y = 0.5f*v.y*(1.0f + erff(v.y*0.70710678118654752f));
                    v.z = 0.5f*v.z*(1.0f + erff(v.z*0.70710678118654752f));
                    v.w = 0.5f*v.w*(1.0f + erff(v.w*0.70710678118654752f));
                }
                *(float4*)(C + off) = v;
            }
        }
    }
}

/* ---------------- Attention: one block per (head, batch) ----------------
   Q,K,V (197x64 fp32 each, padded to 65 cols) + per-warp prob rows in smem */
#define QKV_PAD 65
#define QKV_SZ  (Nx*QKV_PAD)            /* 12805 */
#define SMEM_ATTN_FLOATS (3*QKV_SZ + 8*200)
__global__ __launch_bounds__(256) void attn_kernel(const float* __restrict__ qkv,
                                                   float* __restrict__ out,
                                                   float* __restrict__ clsh)
{
    extern __shared__ float sm[];
    float* Qs = sm;
    float* Ks = sm + QKV_SZ;
    float* Vs = sm + 2*QKV_SZ;
    float* Pb = sm + 3*QKV_SZ;
    int h = blockIdx.x, b = blockIdx.y;
    int tid = threadIdx.x, warp = tid>>5, lane = tid&31;

    const float* base = qkv + (size_t)b*Nx*2304 + h*64;
    for (int i = tid; i < Nx*64; i += 256){
        int n = i>>6, c = i&63;
        size_t s = (size_t)n*2304 + c;
        Qs[n*QKV_PAD+c] = base[s];
        Ks[n*QKV_PAD+c] = base[s+768];
        Vs[n*QKV_PAD+c] = base[s+1536];
    }
    __syncthreads();

    float* pb = Pb + warp*200;
    for (int i = warp; i < Nx; i += 8){
        const float* qr = Qs + i*QKV_PAD;
        float sc[7];
        int joff[7];
        #pragma unroll
        for (int t=0;t<7;t++){ sc[t]=0.f; int j=lane+32*t; joff[t] = (j<Nx ? j : 0)*QKV_PAD; }
        #pragma unroll 4
        for (int c=0;c<64;c++){
            float qc = qr[c];
            #pragma unroll
            for (int t=0;t<7;t++) sc[t] = fmaf(qc, Ks[joff[t]+c], sc[t]);
        }
        float mx = -3.0e38f;
        #pragma unroll
        for (int t=0;t<7;t++){
            int j=lane+32*t;
            sc[t] = (j<Nx) ? sc[t]*0.125f : -3.0e38f;
            mx = fmaxf(mx, sc[t]);
        }
        #pragma unroll
        for (int o=16;o;o>>=1) mx = fmaxf(mx, __shfl_xor_sync(0xffffffffu, mx, o));
        float sum = 0.f;
        #pragma unroll
        for (int t=0;t<7;t++){
            int j=lane+32*t;
            float e = (j<Nx) ? expf(sc[t]-mx) : 0.f;
            sc[t]=e; sum+=e;
        }
        #pragma unroll
        for (int o=16;o;o>>=1) sum += __shfl_xor_sync(0xffffffffu, sum, o);
        float inv = 1.0f/sum;
        #pragma unroll
        for (int t=0;t<7;t++){
            int j=lane+32*t;
            if (j<Nx) pb[j] = sc[t]*inv;
        }
        __syncwarp();
        if (i == 0){
            #pragma unroll
            for (int t=0;t<7;t++){
                int j=lane+32*t;
                if (j>=1 && j<Nx) clsh[((size_t)b*Hx + h)*196 + (j-1)] = sc[t]*inv;
            }
        }
        float o0=0.f, o1=0.f;
        for (int j=0;j<Nx;j++){
            float p = pb[j];
            o0 = fmaf(p, Vs[j*QKV_PAD+lane], o0);
            o1 = fmaf(p, Vs[j*QKV_PAD+lane+32], o1);
        }
        size_t oo = (size_t)(b*Nx + i)*Cx + h*64;
        out[oo + lane]      = o0;
        out[oo + lane + 32] = o1;
        __syncwarp();
    }
}

/* ---------------- cls_attn = mean over heads (deterministic) ---------------- */
__global__ void cls_mean_kernel()
{
    int b = blockIdx.x, j = threadIdx.x;
    if (j < 196){
        float s = 0.f;
        #pragma unroll
        for (int h=0; h<Hx; h++) s += g_clsh[((size_t)b*Hx + h)*196 + j];
        g_cls[b*196 + j] = s * (1.0f/12.0f);
    }
}

/* ---------------- top-k (138 of 196) via bitonic sort + complement --------- */
__global__ __launch_bounds__(256) void topk_kernel()
{
    __shared__ float v[256];
    __shared__ int   id[256];
    __shared__ unsigned char sel[196];
    int b = blockIdx.x, t = threadIdx.x;
    v[t]  = (t < 196) ? g_cls[b*196 + t] : -3.0e38f;
    id[t] = t;
    __syncthreads();
    for (int k=2;k<=256;k<<=1){
        for (int j=k>>1;j>0;j>>=1){
            int ixj = t ^ j;
            if (ixj > t){
                float va=v[t], vb=v[ixj];
                int   ia=id[t], ib=id[ixj];
                bool aWorse = (va < vb) || (va == vb && ia > ib);
                bool dirDesc = ((t & k) == 0);
                bool doswap = dirDesc ? aWorse : !aWorse;
                if (doswap){ v[t]=vb; v[ixj]=va; id[t]=ib; id[ixj]=ia; }
            }
            __syncthreads();
        }
    }
    if (t < LEFT) g_idx[b*LEFT + t] = id[t];
    if (t < 196) sel[t] = 0;
    __syncthreads();
    if (t < LEFT) sel[id[t]] = 1;
    __syncthreads();
    if (t == 0){
        int c = 0;
        for (int j=0;j<196;j++) if (!sel[j]) g_cmp[b*CMPL + (c++)] = j;
    }
}

/* ---------------- gathers (padded for the distance GEMM) ---------------- */
__global__ __launch_bounds__(256) void gather_xo_kernel()
{
    int l = blockIdx.x, b = blockIdx.y, t = threadIdx.x;
    float* dst = g_XO + ((size_t)b*144 + l)*Cx;
    float ss = 0.f;
    if (l < LEFT){
        int j = g_idx[b*LEFT + l];
        const float* src = g_x1 + ((size_t)(b*Nx) + 1 + j)*Cx;
        #pragma unroll
        for (int r=0;r<3;r++){
            float vv = src[t + r*256];
            dst[t + r*256] = vv;
            ss += vv*vv;
        }
    } else {
        #pragma unroll
        for (int r=0;r<3;r++) dst[t + r*256] = 0.f;
    }
    __shared__ float sr[8];
    #pragma unroll
    for (int o=16;o;o>>=1) ss += __shfl_xor_sync(0xffffffffu, ss, o);
    if ((t&31)==0) sr[t>>5] = ss;
    __syncthreads();
    if (t == 0 && l < LEFT){
        float tot = 0.f;
        #pragma unroll
        for (int i=0;i<8;i++) tot += sr[i];
        g_nrm[b*LEFT + l] = sqrtf(tot);
    }
}

__global__ __launch_bounds__(256) void gather_nt_kernel()
{
    int m = blockIdx.x, b = blockIdx.y, t = threadIdx.x;
    float* dst = g_NT + ((size_t)b*64 + m)*Cx;
    if (m < CMPL){
        int j = g_cmp[b*CMPL + m];
        const float* src = g_x1 + ((size_t)(b*Nx) + 1 + j)*Cx;
        #pragma unroll
        for (int r=0;r<3;r++) dst[t + r*256] = src[t + r*256];
    } else {
        #pragma unroll
        for (int r=0;r<3;r++) dst[t + r*256] = 0.f;
    }
}

/* ---------------- distance GEMM: per batch, D[64pad,144pad] = NT @ XO^T ---- */
__global__ __launch_bounds__(256) void dist_kernel()
{
    __shared__ float NTs[64*33];
    __shared__ float XOs[144*33];
    int b = blockIdx.x, tid = threadIdx.x;
    int tx = tid & 15, ty = tid >> 4;
    const float* NTb = g_NT + (size_t)b*64*Cx;
    const float* XOb = g_XO + (size_t)b*144*Cx;
    float acc[4][9];
    #pragma unroll
    for (int i=0;i<4;i++)
        #pragma unroll
        for (int j=0;j<9;j++) acc[i][j]=0.f;

    for (int k0=0;k0<Cx;k0+=32){
        for (int i=tid;i<64*32;i+=256){ int m=i>>5, kk=i&31; NTs[m*33+kk]=NTb[(size_t)m*Cx+k0+kk]; }
        for (int i=tid;i<144*32;i+=256){ int l=i>>5, kk=i&31; XOs[l*33+kk]=XOb[(size_t)l*Cx+k0+kk]; }
        __syncthreads();
        #pragma unroll 8
        for (int kk=0;kk<32;kk++){
            float a[4], bb2[9];
            #pragma unroll
            for (int ii=0;ii<4;ii++) a[ii]  = NTs[(ty*4+ii)*33 + kk];
            #pragma unroll
            for (int jj=0;jj<9;jj++) bb2[jj]= XOs[(tx*9+jj)*33 + kk];
            #pragma unroll
            for (int ii=0;ii<4;ii++)
                #pragma unroll
                for (int jj=0;jj<9;jj++)
                    acc[ii][jj] = fmaf(a[ii], bb2[jj], acc[ii][jj]);
        }
        __syncthreads();
    }
    #pragma unroll
    for (int ii=0;ii<4;ii++)
        #pragma unroll
        for (int jj=0;jj<9;jj++)
            g_D[(size_t)b*9216 + (ty*4+ii)*144 + (tx*9+jj)] = acc[ii][jj];
}

/* ---------------- argmax over topk (first-max tie rule, matches jnp) ------- */
__global__ void argmax_kernel()
{
    int m = blockIdx.x, b = blockIdx.y, lane = threadIdx.x;
    const float* Dr = g_D + (size_t)b*9216 + m*144;
    float best = -3.0e38f; int bi = 1<<30;
    for (int l=lane; l<LEFT; l+=32){
        float v = Dr[l] / g_nrm[b*LEFT + l];
        if (v > best || (v == best && l < bi)){ best = v; bi = l; }
    }
    #pragma unroll
    for (int o=16;o;o>>=1){
        float v2 = __shfl_xor_sync(0xffffffffu, best, o);
        int   i2 = __shfl_xor_sync(0xffffffffu, bi,   o);
        if (v2 > best || (v2 == best && i2 < bi)){ best = v2; bi = i2; }
    }
    if (lane == 0) g_node[b*CMPL + m] = bi;
}

/* ---------------- deterministic merge (no atomics): one block per (l,b) ---- */
__global__ __launch_bounds__(256) void merge_kernel()
{
    int l = blockIdx.x, b = blockIdx.y, t = threadIdx.x;
    int jt = g_idx[b*LEFT + l];
    float w = g_cls[b*196 + jt];
    const float* src = g_x1 + ((size_t)(b*Nx) + 1 + jt)*Cx;
    float a0 = src[t]*w, a1 = src[t+256]*w, a2 = src[t+512]*w;
    float tka = w;
    for (int m=0;m<CMPL;m++){
        if (g_node[b*CMPL + m] == l){
            int jm = g_cmp[b*CMPL + m];
            float wm = g_cls[b*196 + jm];
            const float* s2 = g_x1 + ((size_t)(b*Nx) + 1 + jm)*Cx;
            a0 += s2[t]*wm; a1 += s2[t+256]*wm; a2 += s2[t+512]*wm;
            tka += wm;
        }
    }
    float* dst = g_xm + ((size_t)(b*NM) + 1 + l)*Cx;
    dst[t]     = a0 / tka;
    dst[t+256] = a1 / tka;
    dst[t+512] = a2 / tka;
}

__global__ void copy_cls_kernel()
{
    int b = blockIdx.x, t = threadIdx.x;
    const float* s = g_x1 + (size_t)b*Nx*Cx;
    float* d = g_xm + (size_t)b*NM*Cx;
    #pragma unroll
    for (int r=0;r<3;r++) d[t + r*256] = s[t + r*256];
}

/* ---------------- host launcher ---------------- */
extern "C" void kernel_launch(void* const* d_in, const int* in_sizes, int n_in,
                              void* d_out, int out_size)
{
    const float* x     = (const float*)d_in[0];
    const float* n1w   = (const float*)d_in[1];
    const float* n1b   = (const float*)d_in[2];
    const float* qkvw  = (const float*)d_in[3];
    const float* projw = (const float*)d_in[4];
    const float* projb = (const float*)d_in[5];
    const float* n2w   = (const float*)d_in[6];
    const float* n2b   = (const float*)d_in[7];
    const float* fc1w  = (const float*)d_in[8];
    const float* fc1b  = (const float*)d_in[9];
    const float* fc2w  = (const float*)d_in[10];
    const float* fc2b  = (const float*)d_in[11];
    float* out = (float*)d_out;

    void *p;
    cudaGetSymbolAddress(&p, g_xn);   float* pxn  = (float*)p;
    cudaGetSymbolAddress(&p, g_qkv);  float* pqkv = (float*)p;
    cudaGetSymbolAddress(&p, g_ao);   float* pao  = (float*)p;
    cudaGetSymbolAddress(&p, g_x1);   float* px1  = (float*)p;
    cudaGetSymbolAddress(&p, g_clsh); float* pclsh= (float*)p;
    cudaGetSymbolAddress(&p, g_xm);   float* pxm  = (float*)p;
    cudaGetSymbolAddress(&p, g_xn2);  float* pxn2 = (float*)p;
    cudaGetSymbolAddress(&p, g_h1);   float* ph1  = (float*)p;

    /* 1) LN1 */
    ln_kernel<<<NROWS, 256>>>(x, n1w, n1b, pxn);

    /* 2) QKV GEMM: [25216,768] x [768,2304] */
    sgemm2<0><<<dim3(2304/128, NROWS/128), 256>>>(pxn, qkvw, nullptr, nullptr, pqkv,
                                                  NROWS, 2304, Cx);

    /* 3) attention per (head, batch) */
    cudaFuncSetAttribute(attn_kernel, cudaFuncAttributeMaxDynamicSharedMemorySize,
                         SMEM_ATTN_FLOATS*4);
    attn_kernel<<<dim3(Hx, Bx), 256, SMEM_ATTN_FLOATS*4>>>(pqkv, pao, pclsh);

    /* 4) proj GEMM + bias + residual(x) -> x1 */
    sgemm2<2><<<dim3(Cx/128, NROWS/128), 256>>>(pao, projw, projb, x, px1,
                                                NROWS, Cx, Cx);

    /* 5) cls attention mean over heads, 6) top-k + complement */
    cls_mean_kernel<<<Bx, 256>>>();
    topk_kernel<<<Bx, 256>>>();

    /* 7) gathers + norms, 8) cosine distance GEMM, 9) argmax */
    gather_xo_kernel<<<dim3(144, Bx), 256>>>();
    gather_nt_kernel<<<dim3(64, Bx), 256>>>();
    dist_kernel<<<Bx, 256>>>();
    argmax_kernel<<<dim3(CMPL, Bx), 32>>>();

    /* 10) deterministic merge + cls copy -> xm */
    merge_kernel<<<dim3(LEFT, Bx), 256>>>();
    copy_cls_kernel<<<Bx, 256>>>();

    /* 11) LN2, 12) fc1+GELU, 13) fc2+bias+residual -> out */
    ln_kernel<<<M2, 256>>>(pxm, n2w, n2b, pxn2);
    sgemm2<3><<<dim3(FF/128, M2/128), 256>>>(pxn2, fc1w, fc1b, nullptr, ph1,
                                             M2, FF, Cx);
    sgemm2<2><<<dim3(Cx/128, M2/128), 256>>>(ph1, fc2w, fc2b, pxm, out,
                                             M2, Cx, FF);
    (void)in_sizes; (void)n_in; (void)out_size;
}

// round 5
// speedup vs baseline: 1.3929x; 1.3929x over previous
#include <cuda_runtime.h>
#include <math.h>
#include <stdint.h>

#define Bx   128
#define Nx   197
#define Cx   768
#define Hx   12
#define Dx   64
#define NROWS 25216      /* Bx*Nx */
#define LEFT 138
#define CMPL 58
#define NM   139
#define M2   17792       /* Bx*NM */
#define FF   3072

/* ---------------- device scratch (no allocations allowed) ---------------- */
__device__ float g_xn [NROWS*Cx];
__device__ float g_qkv[NROWS*3*Cx];
__device__ float g_ao [NROWS*Cx];
__device__ float g_x1 [NROWS*Cx];
__device__ float g_clsh[Bx*Hx*196];
__device__ float g_cls[Bx*196];
__device__ int   g_idx[Bx*LEFT];
__device__ int   g_cmp[Bx*CMPL];
__device__ float g_NT[Bx*64*Cx];
__device__ float g_XO[Bx*144*Cx];
__device__ float g_nrm[Bx*LEFT];
__device__ float g_D[Bx*64*144];
__device__ int   g_node[Bx*CMPL];
__device__ float g_xm [M2*Cx];
__device__ float g_xn2[M2*Cx];
__device__ float g_h1 [M2*FF];

/* ---------------- LayerNorm: one block per row, 256 thr, C=768 ---------------- */
__global__ __launch_bounds__(256) void ln_kernel(const float* __restrict__ x,
                                                 const float* __restrict__ w,
                                                 const float* __restrict__ bb,
                                                 float* __restrict__ y)
{
    int row = blockIdx.x;
    const float* xr = x + (size_t)row * Cx;
    float* yr = y + (size_t)row * Cx;
    int t = threadIdx.x;
    float v0 = xr[t], v1 = xr[t+256], v2 = xr[t+512];
    float s = v0+v1+v2;
    float q = v0*v0 + v1*v1 + v2*v2;
    __shared__ float sred[16];
    #pragma unroll
    for (int o=16;o;o>>=1){ s += __shfl_xor_sync(0xffffffffu,s,o); q += __shfl_xor_sync(0xffffffffu,q,o); }
    if ((t&31)==0){ sred[t>>5] = s; sred[8+(t>>5)] = q; }
    __syncthreads();
    s = 0.f; q = 0.f;
    #pragma unroll
    for (int i=0;i<8;i++){ s += sred[i]; q += sred[8+i]; }
    float mean = s * (1.0f/768.0f);
    float var  = q * (1.0f/768.0f) - mean*mean;
    float rstd = rsqrtf(var + 1e-5f);
    yr[t]     = (v0-mean)*rstd*w[t]     + bb[t];
    yr[t+256] = (v1-mean)*rstd*w[t+256] + bb[t+256];
    yr[t+512] = (v2-mean)*rstd*w[t+512] + bb[t+512];
}

/* ---------------- SGEMM 128x128x8, 256 thr, 8x8/thread, fp32 ----------------
   (proven R1 version: 2 CTAs/SM, occ 24%, issue 65%)
   EPI: 0 = none, 1 = +bias, 2 = +bias+residual, 3 = +bias+exact GELU        */
template<int EPI>
__global__ __launch_bounds__(256) void sgemm(const float* __restrict__ A,
                                             const float* __restrict__ B,
                                             const float* __restrict__ bias,
                                             const float* __restrict__ res,
                                             float* __restrict__ C,
                                             int M, int N, int K)
{
    __shared__ float As[8][128];
    __shared__ float Bs[8][128];
    int tid = threadIdx.x;
    int bm = blockIdx.y << 7, bn = blockIdx.x << 7;
    const float* Ap = A + (size_t)(bm + (tid>>1))*K + ((tid&1)<<2);
    const float* Bp = B + (size_t)(tid>>5)*N + bn + ((tid&31)<<2);
    int tx = tid & 15, ty = tid >> 4;
    int arow = tid>>1, ac = (tid&1)<<2;
    int brow = tid>>5, bc = (tid&31)<<2;
    float acc[8][8];
    #pragma unroll
    for (int i=0;i<8;i++)
        #pragma unroll
        for (int j=0;j<8;j++) acc[i][j] = 0.f;

    for (int k0=0;k0<K;k0+=8){
        float4 av = *(const float4*)Ap; Ap += 8;
        float4 bv = *(const float4*)Bp; Bp += (size_t)8*N;
        As[ac+0][arow]=av.x; As[ac+1][arow]=av.y; As[ac+2][arow]=av.z; As[ac+3][arow]=av.w;
        *(float4*)&Bs[brow][bc] = bv;
        __syncthreads();
        #pragma unroll
        for (int kk=0;kk<8;kk++){
            float a[8], b[8];
            *(float4*)(a)   = *(const float4*)&As[kk][ty<<3];
            *(float4*)(a+4) = *(const float4*)&As[kk][(ty<<3)+4];
            *(float4*)(b)   = *(const float4*)&Bs[kk][tx<<3];
            *(float4*)(b+4) = *(const float4*)&Bs[kk][(tx<<3)+4];
            #pragma unroll
            for (int i=0;i<8;i++)
                #pragma unroll
                for (int j=0;j<8;j++)
                    acc[i][j] = fmaf(a[i], b[j], acc[i][j]);
        }
        __syncthreads();
    }
    #pragma unroll
    for (int i=0;i<8;i++){
        size_t off = (size_t)(bm + (ty<<3) + i)*N + bn + (tx<<3);
        #pragma unroll
        for (int j=0;j<8;j++){
            float v = acc[i][j];
            if (EPI >= 1) v += bias[bn + (tx<<3) + j];
            if (EPI == 2) v += res[off + j];
            if (EPI == 3) v = 0.5f*v*(1.0f + erff(v*0.70710678118654752f));
            C[off + j] = v;
        }
    }
}

/* ---------------- TF32 tensor-core GEMM (mma.sync m16n8k8) ----------------
   128x128x16 tile, 256 thr (8 warps, 2x4 warp grid, 64x32 warp tiles).
   EPI: 2 = +bias+residual, 3 = +bias+exact GELU. Requires M%128==0, N%128==0,
   K%16==0. Used ONLY for selection-free GEMMs (fc1, fc2).                   */
__device__ __forceinline__ uint32_t f2tf(float f){
    uint32_t u; asm("cvt.rna.tf32.f32 %0, %1;" : "=r"(u) : "f"(f)); return u;
}

template<int EPI>
__global__ __launch_bounds__(256) void mma_gemm(const float* __restrict__ A,
                                                const float* __restrict__ B,
                                                const float* __restrict__ bias,
                                                const float* __restrict__ res,
                                                float* __restrict__ C,
                                                int M, int N, int K)
{
    __shared__ float As[2][128][20];   /* padded: frag LDS conflict-free */
    __shared__ float Bs[2][16][136];

    int tid = threadIdx.x;
    int bm = blockIdx.y << 7, bn = blockIdx.x << 7;
    int lane = tid & 31, warp = tid >> 5;
    int wm = (warp >> 2) << 6;         /* 0 or 64  */
    int wn = (warp & 3) << 5;          /* 0,32,64,96 */
    int gq = lane >> 2, gr = lane & 3;

    int ar = tid >> 1, ac = (tid & 1) << 3;
    int br = tid >> 4, bc = (tid & 15) << 3;
    const float* Ag = A + (size_t)(bm + ar)*K + ac;
    const float* Bg = B + (size_t)br*N + bn + bc;

    float acc[4][4][4];
    #pragma unroll
    for (int mi=0;mi<4;mi++)
        #pragma unroll
        for (int ni=0;ni<4;ni++)
            #pragma unroll
            for (int r=0;r<4;r++) acc[mi][ni][r] = 0.f;

    /* prologue: tile 0 */
    {
        float4 a0v = *(const float4*)Ag;
        float4 a1v = *(const float4*)(Ag + 4);
        float4 b0v = *(const float4*)Bg;
        float4 b1v = *(const float4*)(Bg + 4);
        *(float4*)&As[0][ar][ac]   = a0v;
        *(float4*)&As[0][ar][ac+4] = a1v;
        *(float4*)&Bs[0][br][bc]   = b0v;
        *(float4*)&Bs[0][br][bc+4] = b1v;
    }
    __syncthreads();

    int KT = K >> 4;
    for (int kt = 0; kt < KT; kt++){
        int cur = kt & 1;
        float4 na0, na1, nb0, nb1;
        if (kt < KT-1){
            const float* Ag2 = Ag + ((kt+1) << 4);
            const float* Bg2 = Bg + (size_t)((kt+1) << 4) * N;
            na0 = *(const float4*)Ag2;
            na1 = *(const float4*)(Ag2 + 4);
            nb0 = *(const float4*)Bg2;
            nb1 = *(const float4*)(Bg2 + 4);
        }
        #pragma unroll
        for (int ks = 0; ks < 16; ks += 8){
            uint32_t Af[4][4], Bf[4][2];
            #pragma unroll
            for (int mi=0;mi<4;mi++){
                int m0 = wm + (mi<<4) + gq;
                Af[mi][0] = f2tf(As[cur][m0  ][ks+gr]);
                Af[mi][1] = f2tf(As[cur][m0+8][ks+gr]);
                Af[mi][2] = f2tf(As[cur][m0  ][ks+4+gr]);
                Af[mi][3] = f2tf(As[cur][m0+8][ks+4+gr]);
            }
            #pragma unroll
            for (int ni=0;ni<4;ni++){
                int n0 = wn + (ni<<3) + gq;
                Bf[ni][0] = f2tf(Bs[cur][ks+gr  ][n0]);
                Bf[ni][1] = f2tf(Bs[cur][ks+4+gr][n0]);
            }
            #pragma unroll
            for (int mi=0;mi<4;mi++)
                #pragma unroll
                for (int ni=0;ni<4;ni++){
                    asm volatile(
                        "mma.sync.aligned.m16n8k8.row.col.f32.tf32.tf32.f32 "
                        "{%0,%1,%2,%3}, {%4,%5,%6,%7}, {%8,%9}, {%0,%1,%2,%3};"
                        : "+f"(acc[mi][ni][0]), "+f"(acc[mi][ni][1]),
                          "+f"(acc[mi][ni][2]), "+f"(acc[mi][ni][3])
                        : "r"(Af[mi][0]), "r"(Af[mi][1]), "r"(Af[mi][2]), "r"(Af[mi][3]),
                          "r"(Bf[ni][0]), "r"(Bf[ni][1]));
                }
        }
        if (kt < KT-1){
            int nxt = cur ^ 1;
            *(float4*)&As[nxt][ar][ac]   = na0;
            *(float4*)&As[nxt][ar][ac+4] = na1;
            *(float4*)&Bs[nxt][br][bc]   = nb0;
            *(float4*)&Bs[nxt][br][bc+4] = nb1;
            __syncthreads();
        }
    }

    /* epilogue */
    #pragma unroll
    for (int mi=0;mi<4;mi++){
        int row = bm + wm + (mi<<4) + gq;
        #pragma unroll
        for (int ni=0;ni<4;ni++){
            int col = bn + wn + (ni<<3) + (gr<<1);
            float b0 = bias[col], b1 = bias[col+1];
            size_t o0 = (size_t)row*N + col;
            size_t o1 = (size_t)(row+8)*N + col;
            float v00 = acc[mi][ni][0] + b0;
            float v01 = acc[mi][ni][1] + b1;
            float v10 = acc[mi][ni][2] + b0;
            float v11 = acc[mi][ni][3] + b1;
            if (EPI == 2){
                v00 += res[o0];   v01 += res[o0+1];
                v10 += res[o1];   v11 += res[o1+1];
            }
            if (EPI == 3){
                v00 = 0.5f*v00*(1.0f + erff(v00*0.70710678118654752f));
                v01 = 0.5f*v01*(1.0f + erff(v01*0.70710678118654752f));
                v10 = 0.5f*v10*(1.0f + erff(v10*0.70710678118654752f));
                v11 = 0.5f*v11*(1.0f + erff(v11*0.70710678118654752f));
            }
            float2 w0; w0.x = v00; w0.y = v01;
            float2 w1; w1.x = v10; w1.y = v11;
            *(float2*)(C + o0) = w0;
            *(float2*)(C + o1) = w1;
        }
    }
}

/* ---------------- Attention: one block per (head, batch) ----------------
   Q,K,V (197x64 fp32 each, padded to 65 cols) + per-warp prob rows in smem */
#define QKV_PAD 65
#define QKV_SZ  (Nx*QKV_PAD)            /* 12805 */
#define SMEM_ATTN_FLOATS (3*QKV_SZ + 8*200)
__global__ __launch_bounds__(256) void attn_kernel(const float* __restrict__ qkv,
                                                   float* __restrict__ out,
                                                   float* __restrict__ clsh)
{
    extern __shared__ float sm[];
    float* Qs = sm;
    float* Ks = sm + QKV_SZ;
    float* Vs = sm + 2*QKV_SZ;
    float* Pb = sm + 3*QKV_SZ;
    int h = blockIdx.x, b = blockIdx.y;
    int tid = threadIdx.x, warp = tid>>5, lane = tid&31;

    const float* base = qkv + (size_t)b*Nx*2304 + h*64;
    for (int i = tid; i < Nx*64; i += 256){
        int n = i>>6, c = i&63;
        size_t s = (size_t)n*2304 + c;
        Qs[n*QKV_PAD+c] = base[s];
        Ks[n*QKV_PAD+c] = base[s+768];
        Vs[n*QKV_PAD+c] = base[s+1536];
    }
    __syncthreads();

    float* pb = Pb + warp*200;
    for (int i = warp; i < Nx; i += 8){
        const float* qr = Qs + i*QKV_PAD;
        float sc[7];
        int joff[7];
        #pragma unroll
        for (int t=0;t<7;t++){ sc[t]=0.f; int j=lane+32*t; joff[t] = (j<Nx ? j : 0)*QKV_PAD; }
        #pragma unroll 4
        for (int c=0;c<64;c++){
            float qc = qr[c];
            #pragma unroll
            for (int t=0;t<7;t++) sc[t] = fmaf(qc, Ks[joff[t]+c], sc[t]);
        }
        float mx = -3.0e38f;
        #pragma unroll
        for (int t=0;t<7;t++){
            int j=lane+32*t;
            sc[t] = (j<Nx) ? sc[t]*0.125f : -3.0e38f;
            mx = fmaxf(mx, sc[t]);
        }
        #pragma unroll
        for (int o=16;o;o>>=1) mx = fmaxf(mx, __shfl_xor_sync(0xffffffffu, mx, o));
        float sum = 0.f;
        #pragma unroll
        for (int t=0;t<7;t++){
            int j=lane+32*t;
            float e = (j<Nx) ? expf(sc[t]-mx) : 0.f;
            sc[t]=e; sum+=e;
        }
        #pragma unroll
        for (int o=16;o;o>>=1) sum += __shfl_xor_sync(0xffffffffu, sum, o);
        float inv = 1.0f/sum;
        #pragma unroll
        for (int t=0;t<7;t++){
            int j=lane+32*t;
            if (j<Nx) pb[j] = sc[t]*inv;
        }
        __syncwarp();
        if (i == 0){
            #pragma unroll
            for (int t=0;t<7;t++){
                int j=lane+32*t;
                if (j>=1 && j<Nx) clsh[((size_t)b*Hx + h)*196 + (j-1)] = sc[t]*inv;
            }
        }
        float o0=0.f, o1=0.f;
        for (int j=0;j<Nx;j++){
            float p = pb[j];
            o0 = fmaf(p, Vs[j*QKV_PAD+lane], o0);
            o1 = fmaf(p, Vs[j*QKV_PAD+lane+32], o1);
        }
        size_t oo = (size_t)(b*Nx + i)*Cx + h*64;
        out[oo + lane]      = o0;
        out[oo + lane + 32] = o1;
        __syncwarp();
    }
}

/* ---------------- cls_attn = mean over heads (deterministic) ---------------- */
__global__ void cls_mean_kernel()
{
    int b = blockIdx.x, j = threadIdx.x;
    if (j < 196){
        float s = 0.f;
        #pragma unroll
        for (int h=0; h<Hx; h++) s += g_clsh[((size_t)b*Hx + h)*196 + j];
        g_cls[b*196 + j] = s * (1.0f/12.0f);
    }
}

/* ---------------- top-k (138 of 196) via bitonic sort + complement --------- */
__global__ __launch_bounds__(256) void topk_kernel()
{
    __shared__ float v[256];
    __shared__ int   id[256];
    __shared__ unsigned char sel[196];
    int b = blockIdx.x, t = threadIdx.x;
    v[t]  = (t < 196) ? g_cls[b*196 + t] : -3.0e38f;
    id[t] = t;
    __syncthreads();
    for (int k=2;k<=256;k<<=1){
        for (int j=k>>1;j>0;j>>=1){
            int ixj = t ^ j;
            if (ixj > t){
                float va=v[t], vb=v[ixj];
                int   ia=id[t], ib=id[ixj];
                bool aWorse = (va < vb) || (va == vb && ia > ib);
                bool dirDesc = ((t & k) == 0);
                bool doswap = dirDesc ? aWorse : !aWorse;
                if (doswap){ v[t]=vb; v[ixj]=va; id[t]=ib; id[ixj]=ia; }
            }
            __syncthreads();
        }
    }
    if (t < LEFT) g_idx[b*LEFT + t] = id[t];
    if (t < 196) sel[t] = 0;
    __syncthreads();
    if (t < LEFT) sel[id[t]] = 1;
    __syncthreads();
    if (t == 0){
        int c = 0;
        for (int j=0;j<196;j++) if (!sel[j]) g_cmp[b*CMPL + (c++)] = j;
    }
}

/* ---------------- gathers (padded for the distance GEMM) ---------------- */
__global__ __launch_bounds__(256) void gather_xo_kernel()
{
    int l = blockIdx.x, b = blockIdx.y, t = threadIdx.x;
    float* dst = g_XO + ((size_t)b*144 + l)*Cx;
    float ss = 0.f;
    if (l < LEFT){
        int j = g_idx[b*LEFT + l];
        const float* src = g_x1 + ((size_t)(b*Nx) + 1 + j)*Cx;
        #pragma unroll
        for (int r=0;r<3;r++){
            float vv = src[t + r*256];
            dst[t + r*256] = vv;
            ss += vv*vv;
        }
    } else {
        #pragma unroll
        for (int r=0;r<3;r++) dst[t + r*256] = 0.f;
    }
    __shared__ float sr[8];
    #pragma unroll
    for (int o=16;o;o>>=1) ss += __shfl_xor_sync(0xffffffffu, ss, o);
    if ((t&31)==0) sr[t>>5] = ss;
    __syncthreads();
    if (t == 0 && l < LEFT){
        float tot = 0.f;
        #pragma unroll
        for (int i=0;i<8;i++) tot += sr[i];
        g_nrm[b*LEFT + l] = sqrtf(tot);
    }
}

__global__ __launch_bounds__(256) void gather_nt_kernel()
{
    int m = blockIdx.x, b = blockIdx.y, t = threadIdx.x;
    float* dst = g_NT + ((size_t)b*64 + m)*Cx;
    if (m < CMPL){
        int j = g_cmp[b*CMPL + m];
        const float* src = g_x1 + ((size_t)(b*Nx) + 1 + j)*Cx;
        #pragma unroll
        for (int r=0;r<3;r++) dst[t + r*256] = src[t + r*256];
    } else {
        #pragma unroll
        for (int r=0;r<3;r++) dst[t + r*256] = 0.f;
    }
}

/* ---------------- distance GEMM: per batch, D[64pad,144pad] = NT @ XO^T ---- */
__global__ __launch_bounds__(256) void dist_kernel()
{
    __shared__ float NTs[64*33];
    __shared__ float XOs[144*33];
    int b = blockIdx.x, tid = threadIdx.x;
    int tx = tid & 15, ty = tid >> 4;
    const float* NTb = g_NT + (size_t)b*64*Cx;
    const float* XOb = g_XO + (size_t)b*144*Cx;
    float acc[4][9];
    #pragma unroll
    for (int i=0;i<4;i++)
        #pragma unroll
        for (int j=0;j<9;j++) acc[i][j]=0.f;

    for (int k0=0;k0<Cx;k0+=32){
        for (int i=tid;i<64*32;i+=256){ int m=i>>5, kk=i&31; NTs[m*33+kk]=NTb[(size_t)m*Cx+k0+kk]; }
        for (int i=tid;i<144*32;i+=256){ int l=i>>5, kk=i&31; XOs[l*33+kk]=XOb[(size_t)l*Cx+k0+kk]; }
        __syncthreads();
        #pragma unroll 8
        for (int kk=0;kk<32;kk++){
            float a[4], bb2[9];
            #pragma unroll
            for (int ii=0;ii<4;ii++) a[ii]  = NTs[(ty*4+ii)*33 + kk];
            #pragma unroll
            for (int jj=0;jj<9;jj++) bb2[jj]= XOs[(tx*9+jj)*33 + kk];
            #pragma unroll
            for (int ii=0;ii<4;ii++)
                #pragma unroll
                for (int jj=0;jj<9;jj++)
                    acc[ii][jj] = fmaf(a[ii], bb2[jj], acc[ii][jj]);
        }
        __syncthreads();
    }
    #pragma unroll
    for (int ii=0;ii<4;ii++)
        #pragma unroll
        for (int jj=0;jj<9;jj++)
            g_D[(size_t)b*9216 + (ty*4+ii)*144 + (tx*9+jj)] = acc[ii][jj];
}

/* ---------------- argmax over topk (first-max tie rule, matches jnp) ------- */
__global__ void argmax_kernel()
{
    int m = blockIdx.x, b = blockIdx.y, lane = threadIdx.x;
    const float* Dr = g_D + (size_t)b*9216 + m*144;
    float best = -3.0e38f; int bi = 1<<30;
    for (int l=lane; l<LEFT; l+=32){
        float v = Dr[l] / g_nrm[b*LEFT + l];
        if (v > best || (v == best && l < bi)){ best = v; bi = l; }
    }
    #pragma unroll
    for (int o=16;o;o>>=1){
        float v2 = __shfl_xor_sync(0xffffffffu, best, o);
        int   i2 = __shfl_xor_sync(0xffffffffu, bi,   o);
        if (v2 > best || (v2 == best && i2 < bi)){ best = v2; bi = i2; }
    }
    if (lane == 0) g_node[b*CMPL + m] = bi;
}

/* ---------------- deterministic merge (no atomics): one block per (l,b) ---- */
__global__ __launch_bounds__(256) void merge_kernel()
{
    int l = blockIdx.x, b = blockIdx.y, t = threadIdx.x;
    int jt = g_idx[b*LEFT + l];
    float w = g_cls[b*196 + jt];
    const float* src = g_x1 + ((size_t)(b*Nx) + 1 + jt)*Cx;
    float a0 = src[t]*w, a1 = src[t+256]*w, a2 = src[t+512]*w;
    float tka = w;
    for (int m=0;m<CMPL;m++){
        if (g_node[b*CMPL + m] == l){
            int jm = g_cmp[b*CMPL + m];
            float wm = g_cls[b*196 + jm];
            const float* s2 = g_x1 + ((size_t)(b*Nx) + 1 + jm)*Cx;
            a0 += s2[t]*wm; a1 += s2[t+256]*wm; a2 += s2[t+512]*wm;
            tka += wm;
        }
    }
    float* dst = g_xm + ((size_t)(b*NM) + 1 + l)*Cx;
    dst[t]     = a0 / tka;
    dst[t+256] = a1 / tka;
    dst[t+512] = a2 / tka;
}

__global__ void copy_cls_kernel()
{
    int b = blockIdx.x, t = threadIdx.x;
    const float* s = g_x1 + (size_t)b*Nx*Cx;
    float* d = g_xm + (size_t)b*NM*Cx;
    #pragma unroll
    for (int r=0;r<3;r++) d[t + r*256] = s[t + r*256];
}

/* ---------------- host launcher ---------------- */
extern "C" void kernel_launch(void* const* d_in, const int* in_sizes, int n_in,
                              void* d_out, int out_size)
{
    const float* x     = (const float*)d_in[0];
    const float* n1w   = (const float*)d_in[1];
    const float* n1b   = (const float*)d_in[2];
    const float* qkvw  = (const float*)d_in[3];
    const float* projw = (const float*)d_in[4];
    const float* projb = (const float*)d_in[5];
    const float* n2w   = (const float*)d_in[6];
    const float* n2b   = (const float*)d_in[7];
    const float* fc1w  = (const float*)d_in[8];
    const float* fc1b  = (const float*)d_in[9];
    const float* fc2w  = (const float*)d_in[10];
    const float* fc2b  = (const float*)d_in[11];
    float* out = (float*)d_out;

    void *p;
    cudaGetSymbolAddress(&p, g_xn);   float* pxn  = (float*)p;
    cudaGetSymbolAddress(&p, g_qkv);  float* pqkv = (float*)p;
    cudaGetSymbolAddress(&p, g_ao);   float* pao  = (float*)p;
    cudaGetSymbolAddress(&p, g_x1);   float* px1  = (float*)p;
    cudaGetSymbolAddress(&p, g_clsh); float* pclsh= (float*)p;
    cudaGetSymbolAddress(&p, g_xm);   float* pxm  = (float*)p;
    cudaGetSymbolAddress(&p, g_xn2);  float* pxn2 = (float*)p;
    cudaGetSymbolAddress(&p, g_h1);   float* ph1  = (float*)p;

    /* 1) LN1 */
    ln_kernel<<<NROWS, 256>>>(x, n1w, n1b, pxn);

    /* 2) QKV GEMM: [25216,768] x [768,2304]  (fp32 — feeds top-k selection) */
    sgemm<0><<<dim3(2304/128, NROWS/128), 256>>>(pxn, qkvw, nullptr, nullptr, pqkv,
                                                 NROWS, 2304, Cx);

    /* 3) attention per (head, batch) */
    cudaFuncSetAttribute(attn_kernel, cudaFuncAttributeMaxDynamicSharedMemorySize,
                         SMEM_ATTN_FLOATS*4);
    attn_kernel<<<dim3(Hx, Bx), 256, SMEM_ATTN_FLOATS*4>>>(pqkv, pao, pclsh);

    /* 4) proj GEMM + bias + residual(x) -> x1 (fp32 — feeds argmax selection) */
    sgemm<2><<<dim3(Cx/128, NROWS/128), 256>>>(pao, projw, projb, x, px1,
                                               NROWS, Cx, Cx);

    /* 5) cls attention mean over heads, 6) top-k + complement */
    cls_mean_kernel<<<Bx, 256>>>();
    topk_kernel<<<Bx, 256>>>();

    /* 7) gathers + norms, 8) cosine distance GEMM, 9) argmax */
    gather_xo_kernel<<<dim3(144, Bx), 256>>>();
    gather_nt_kernel<<<dim3(64, Bx), 256>>>();
    dist_kernel<<<Bx, 256>>>();
    argmax_kernel<<<dim3(CMPL, Bx), 32>>>();

    /* 10) deterministic merge + cls copy -> xm */
    merge_kernel<<<dim3(LEFT, Bx), 256>>>();
    copy_cls_kernel<<<Bx, 256>>>();

    /* 11) LN2, 12) fc1+GELU (tf32 TC), 13) fc2+bias+residual (tf32 TC) -> out */
    ln_kernel<<<M2, 256>>>(pxm, n2w, n2b, pxn2);
    mma_gemm<3><<<dim3(FF/128, M2/128), 256>>>(pxn2, fc1w, fc1b, nullptr, ph1,
                                               M2, FF, Cx);
    mma_gemm<2><<<dim3(Cx/128, M2/128), 256>>>(ph1, fc2w, fc2b, pxm, out,
                                               M2, Cx, FF);
    (void)in_sizes; (void)n_in; (void)out_size;
}

// round 6
// speedup vs baseline: 1.4577x; 1.0465x over previous
#include <cuda_runtime.h>
#include <math.h>
#include <stdint.h>

#define Bx   128
#define Nx   197
#define Cx   768
#define Hx   12
#define Dx   64
#define NROWS 25216      /* Bx*Nx */
#define LEFT 138
#define CMPL 58
#define NM   139
#define M2   17792       /* Bx*NM */
#define FF   3072

/* ---------------- device scratch (no allocations allowed) ---------------- */
__device__ float g_xn [NROWS*Cx];
__device__ float g_qkv[NROWS*3*Cx];
__device__ float g_ao [NROWS*Cx];
__device__ float g_x1 [NROWS*Cx];
__device__ float g_clsh[Bx*Hx*196];
__device__ float g_cls[Bx*196];
__device__ int   g_idx[Bx*LEFT];
__device__ int   g_cmp[Bx*CMPL];
__device__ float g_NT[Bx*64*Cx];
__device__ float g_XO[Bx*144*Cx];
__device__ float g_nrm[Bx*LEFT];
__device__ float g_D[Bx*64*144];
__device__ int   g_node[Bx*CMPL];
__device__ float g_xm [M2*Cx];
__device__ float g_xn2[M2*Cx];
__device__ float g_h1 [M2*FF];

/* ---------------- cp.async helpers ---------------- */
__device__ __forceinline__ void cpasync16(uint32_t d, const void* s){
    asm volatile("cp.async.cg.shared.global [%0], [%1], 16;" :: "r"(d), "l"(s));
}
__device__ __forceinline__ void cp_commit(){ asm volatile("cp.async.commit_group;"); }
__device__ __forceinline__ void cp_wait0(){ asm volatile("cp.async.wait_group 0;"); }

/* ---------------- LayerNorm: one block per row, 256 thr, C=768 ---------------- */
__global__ __launch_bounds__(256) void ln_kernel(const float* __restrict__ x,
                                                 const float* __restrict__ w,
                                                 const float* __restrict__ bb,
                                                 float* __restrict__ y)
{
    int row = blockIdx.x;
    const float* xr = x + (size_t)row * Cx;
    float* yr = y + (size_t)row * Cx;
    int t = threadIdx.x;
    float v0 = xr[t], v1 = xr[t+256], v2 = xr[t+512];
    float s = v0+v1+v2;
    float q = v0*v0 + v1*v1 + v2*v2;
    __shared__ float sred[16];
    #pragma unroll
    for (int o=16;o;o>>=1){ s += __shfl_xor_sync(0xffffffffu,s,o); q += __shfl_xor_sync(0xffffffffu,q,o); }
    if ((t&31)==0){ sred[t>>5] = s; sred[8+(t>>5)] = q; }
    __syncthreads();
    s = 0.f; q = 0.f;
    #pragma unroll
    for (int i=0;i<8;i++){ s += sred[i]; q += sred[8+i]; }
    float mean = s * (1.0f/768.0f);
    float var  = q * (1.0f/768.0f) - mean*mean;
    float rstd = rsqrtf(var + 1e-5f);
    yr[t]     = (v0-mean)*rstd*w[t]     + bb[t];
    yr[t+256] = (v1-mean)*rstd*w[t+256] + bb[t+256];
    yr[t+512] = (v2-mean)*rstd*w[t+512] + bb[t+512];
}

/* ---------------- SGEMM 128x128x8, 256 thr, 8x8/thread, fp32 ----------------
   (proven R1 version: 2 CTAs/SM, occ 24%, issue 65%)
   EPI: 0 = none, 1 = +bias, 2 = +bias+residual, 3 = +bias+exact GELU        */
template<int EPI>
__global__ __launch_bounds__(256) void sgemm(const float* __restrict__ A,
                                             const float* __restrict__ B,
                                             const float* __restrict__ bias,
                                             const float* __restrict__ res,
                                             float* __restrict__ C,
                                             int M, int N, int K)
{
    __shared__ float As[8][128];
    __shared__ float Bs[8][128];
    int tid = threadIdx.x;
    int bm = blockIdx.y << 7, bn = blockIdx.x << 7;
    const float* Ap = A + (size_t)(bm + (tid>>1))*K + ((tid&1)<<2);
    const float* Bp = B + (size_t)(tid>>5)*N + bn + ((tid&31)<<2);
    int tx = tid & 15, ty = tid >> 4;
    int arow = tid>>1, ac = (tid&1)<<2;
    int brow = tid>>5, bc = (tid&31)<<2;
    float acc[8][8];
    #pragma unroll
    for (int i=0;i<8;i++)
        #pragma unroll
        for (int j=0;j<8;j++) acc[i][j] = 0.f;

    for (int k0=0;k0<K;k0+=8){
        float4 av = *(const float4*)Ap; Ap += 8;
        float4 bv = *(const float4*)Bp; Bp += (size_t)8*N;
        As[ac+0][arow]=av.x; As[ac+1][arow]=av.y; As[ac+2][arow]=av.z; As[ac+3][arow]=av.w;
        *(float4*)&Bs[brow][bc] = bv;
        __syncthreads();
        #pragma unroll
        for (int kk=0;kk<8;kk++){
            float a[8], b[8];
            *(float4*)(a)   = *(const float4*)&As[kk][ty<<3];
            *(float4*)(a+4) = *(const float4*)&As[kk][(ty<<3)+4];
            *(float4*)(b)   = *(const float4*)&Bs[kk][tx<<3];
            *(float4*)(b+4) = *(const float4*)&Bs[kk][(tx<<3)+4];
            #pragma unroll
            for (int i=0;i<8;i++)
                #pragma unroll
                for (int j=0;j<8;j++)
                    acc[i][j] = fmaf(a[i], b[j], acc[i][j]);
        }
        __syncthreads();
    }
    #pragma unroll
    for (int i=0;i<8;i++){
        size_t off = (size_t)(bm + (ty<<3) + i)*N + bn + (tx<<3);
        #pragma unroll
        for (int j=0;j<8;j++){
            float v = acc[i][j];
            if (EPI >= 1) v += bias[bn + (tx<<3) + j];
            if (EPI == 2) v += res[off + j];
            if (EPI == 3) v = 0.5f*v*(1.0f + erff(v*0.70710678118654752f));
            C[off + j] = v;
        }
    }
}

/* ---------------- TF32 tensor-core GEMM v2 (mma.sync m16n8k8) --------------
   128x128x16 tile, 256 thr (8 warps, 2x4 warp grid, 64x32 warp tiles).
   v2: cp.async staging (copy kt+1 overlaps compute kt), raw-fp32-bit tf32
   feed (truncation; fc1/fc2 are selection-free so the 2x rounding error is
   benign), __launch_bounds__(256,2) for 2 CTAs/SM.
   EPI: 2 = +bias+residual, 3 = +bias+exact GELU. M%128==0, N%128==0, K%16==0 */
template<int EPI>
__global__ __launch_bounds__(256, 2) void mma_gemm(const float* __restrict__ A,
                                                   const float* __restrict__ B,
                                                   const float* __restrict__ bias,
                                                   const float* __restrict__ res,
                                                   float* __restrict__ C,
                                                   int M, int N, int K)
{
    __shared__ float As[2][128][20];   /* padded: frag LDS conflict-free */
    __shared__ float Bs[2][16][136];

    int tid = threadIdx.x;
    int bm = blockIdx.y << 7, bn = blockIdx.x << 7;
    int lane = tid & 31, warp = tid >> 5;
    int wm = (warp >> 2) << 6;         /* 0 or 64  */
    int wn = (warp & 3) << 5;          /* 0,32,64,96 */
    int gq = lane >> 2, gr = lane & 3;

    int ar = tid >> 1, ac = (tid & 1) << 3;
    int br = tid >> 4, bc = (tid & 15) << 3;
    const float* Ag = A + (size_t)(bm + ar)*K + ac;
    const float* Bg = B + (size_t)br*N + bn + bc;

    uint32_t sA = (uint32_t)__cvta_generic_to_shared(&As[0][0][0]);
    uint32_t sB = (uint32_t)__cvta_generic_to_shared(&Bs[0][0][0]);
    uint32_t aDst0 = sA + (uint32_t)(ar*80 + ac*4);
    uint32_t bDst0 = sB + (uint32_t)(br*544 + bc*4);
    const uint32_t A_BUF = 128*20*4, B_BUF = 16*136*4;

    float acc[4][4][4];
    #pragma unroll
    for (int mi=0;mi<4;mi++)
        #pragma unroll
        for (int ni=0;ni<4;ni++)
            #pragma unroll
            for (int r=0;r<4;r++) acc[mi][ni][r] = 0.f;

    /* prologue: stage tile 0 */
    cpasync16(aDst0,      Ag);
    cpasync16(aDst0 + 16, Ag + 4);
    cpasync16(bDst0,      Bg);
    cpasync16(bDst0 + 16, Bg + 4);
    cp_commit();

    int KT = K >> 4;
    for (int kt = 0; kt < KT; kt++){
        int cur = kt & 1;
        cp_wait0();
        __syncthreads();               /* all copies of tile kt visible; all
                                          warps done reading buffer cur^1    */
        if (kt < KT-1){
            int nxt = cur ^ 1;
            const float* Ag2 = Ag + ((kt+1) << 4);
            const float* Bg2 = Bg + (size_t)((kt+1) << 4) * N;
            uint32_t ad = aDst0 + (uint32_t)nxt * A_BUF;
            uint32_t bd = bDst0 + (uint32_t)nxt * B_BUF;
            cpasync16(ad,      Ag2);
            cpasync16(ad + 16, Ag2 + 4);
            cpasync16(bd,      Bg2);
            cpasync16(bd + 16, Bg2 + 4);
            cp_commit();
        }
        #pragma unroll
        for (int ks = 0; ks < 16; ks += 8){
            uint32_t Af[4][4], Bf[4][2];
            #pragma unroll
            for (int mi=0;mi<4;mi++){
                int m0 = wm + (mi<<4) + gq;
                Af[mi][0] = __float_as_uint(As[cur][m0  ][ks+gr]);
                Af[mi][1] = __float_as_uint(As[cur][m0+8][ks+gr]);
                Af[mi][2] = __float_as_uint(As[cur][m0  ][ks+4+gr]);
                Af[mi][3] = __float_as_uint(As[cur][m0+8][ks+4+gr]);
            }
            #pragma unroll
            for (int ni=0;ni<4;ni++){
                int n0 = wn + (ni<<3) + gq;
                Bf[ni][0] = __float_as_uint(Bs[cur][ks+gr  ][n0]);
                Bf[ni][1] = __float_as_uint(Bs[cur][ks+4+gr][n0]);
            }
            #pragma unroll
            for (int mi=0;mi<4;mi++)
                #pragma unroll
                for (int ni=0;ni<4;ni++){
                    asm volatile(
                        "mma.sync.aligned.m16n8k8.row.col.f32.tf32.tf32.f32 "
                        "{%0,%1,%2,%3}, {%4,%5,%6,%7}, {%8,%9}, {%0,%1,%2,%3};"
                        : "+f"(acc[mi][ni][0]), "+f"(acc[mi][ni][1]),
                          "+f"(acc[mi][ni][2]), "+f"(acc[mi][ni][3])
                        : "r"(Af[mi][0]), "r"(Af[mi][1]), "r"(Af[mi][2]), "r"(Af[mi][3]),
                          "r"(Bf[ni][0]), "r"(Bf[ni][1]));
                }
        }
    }

    /* epilogue */
    #pragma unroll
    for (int mi=0;mi<4;mi++){
        int row = bm + wm + (mi<<4) + gq;
        #pragma unroll
        for (int ni=0;ni<4;ni++){
            int col = bn + wn + (ni<<3) + (gr<<1);
            float b0 = bias[col], b1 = bias[col+1];
            size_t o0 = (size_t)row*N + col;
            size_t o1 = (size_t)(row+8)*N + col;
            float v00 = acc[mi][ni][0] + b0;
            float v01 = acc[mi][ni][1] + b1;
            float v10 = acc[mi][ni][2] + b0;
            float v11 = acc[mi][ni][3] + b1;
            if (EPI == 2){
                v00 += res[o0];   v01 += res[o0+1];
                v10 += res[o1];   v11 += res[o1+1];
            }
            if (EPI == 3){
                v00 = 0.5f*v00*(1.0f + erff(v00*0.70710678118654752f));
                v01 = 0.5f*v01*(1.0f + erff(v01*0.70710678118654752f));
                v10 = 0.5f*v10*(1.0f + erff(v10*0.70710678118654752f));
                v11 = 0.5f*v11*(1.0f + erff(v11*0.70710678118654752f));
            }
            float2 w0; w0.x = v00; w0.y = v01;
            float2 w1; w1.x = v10; w1.y = v11;
            *(float2*)(C + o0) = w0;
            *(float2*)(C + o1) = w1;
        }
    }
}

/* ---------------- Attention: one block per (head, batch) ----------------
   Q,K,V (197x64 fp32 each, padded to 65 cols) + per-warp prob rows in smem */
#define QKV_PAD 65
#define QKV_SZ  (Nx*QKV_PAD)            /* 12805 */
#define SMEM_ATTN_FLOATS (3*QKV_SZ + 8*200)
__global__ __launch_bounds__(256) void attn_kernel(const float* __restrict__ qkv,
                                                   float* __restrict__ out,
                                                   float* __restrict__ clsh)
{
    extern __shared__ float sm[];
    float* Qs = sm;
    float* Ks = sm + QKV_SZ;
    float* Vs = sm + 2*QKV_SZ;
    float* Pb = sm + 3*QKV_SZ;
    int h = blockIdx.x, b = blockIdx.y;
    int tid = threadIdx.x, warp = tid>>5, lane = tid&31;

    const float* base = qkv + (size_t)b*Nx*2304 + h*64;
    for (int i = tid; i < Nx*64; i += 256){
        int n = i>>6, c = i&63;
        size_t s = (size_t)n*2304 + c;
        Qs[n*QKV_PAD+c] = base[s];
        Ks[n*QKV_PAD+c] = base[s+768];
        Vs[n*QKV_PAD+c] = base[s+1536];
    }
    __syncthreads();

    float* pb = Pb + warp*200;
    for (int i = warp; i < Nx; i += 8){
        const float* qr = Qs + i*QKV_PAD;
        float sc[7];
        int joff[7];
        #pragma unroll
        for (int t=0;t<7;t++){ sc[t]=0.f; int j=lane+32*t; joff[t] = (j<Nx ? j : 0)*QKV_PAD; }
        #pragma unroll 4
        for (int c=0;c<64;c++){
            float qc = qr[c];
            #pragma unroll
            for (int t=0;t<7;t++) sc[t] = fmaf(qc, Ks[joff[t]+c], sc[t]);
        }
        float mx = -3.0e38f;
        #pragma unroll
        for (int t=0;t<7;t++){
            int j=lane+32*t;
            sc[t] = (j<Nx) ? sc[t]*0.125f : -3.0e38f;
            mx = fmaxf(mx, sc[t]);
        }
        #pragma unroll
        for (int o=16;o;o>>=1) mx = fmaxf(mx, __shfl_xor_sync(0xffffffffu, mx, o));
        float sum = 0.f;
        #pragma unroll
        for (int t=0;t<7;t++){
            int j=lane+32*t;
            float e = (j<Nx) ? expf(sc[t]-mx) : 0.f;
            sc[t]=e; sum+=e;
        }
        #pragma unroll
        for (int o=16;o;o>>=1) sum += __shfl_xor_sync(0xffffffffu, sum, o);
        float inv = 1.0f/sum;
        #pragma unroll
        for (int t=0;t<7;t++){
            int j=lane+32*t;
            if (j<Nx) pb[j] = sc[t]*inv;
        }
        __syncwarp();
        if (i == 0){
            #pragma unroll
            for (int t=0;t<7;t++){
                int j=lane+32*t;
                if (j>=1 && j<Nx) clsh[((size_t)b*Hx + h)*196 + (j-1)] = sc[t]*inv;
            }
        }
        float o0=0.f, o1=0.f;
        for (int j=0;j<Nx;j++){
            float p = pb[j];
            o0 = fmaf(p, Vs[j*QKV_PAD+lane], o0);
            o1 = fmaf(p, Vs[j*QKV_PAD+lane+32], o1);
        }
        size_t oo = (size_t)(b*Nx + i)*Cx + h*64;
        out[oo + lane]      = o0;
        out[oo + lane + 32] = o1;
        __syncwarp();
    }
}

/* ---------------- cls_attn = mean over heads (deterministic) ---------------- */
__global__ void cls_mean_kernel()
{
    int b = blockIdx.x, j = threadIdx.x;
    if (j < 196){
        float s = 0.f;
        #pragma unroll
        for (int h=0; h<Hx; h++) s += g_clsh[((size_t)b*Hx + h)*196 + j];
        g_cls[b*196 + j] = s * (1.0f/12.0f);
    }
}

/* ---------------- top-k (138 of 196) via bitonic sort + complement --------- */
__global__ __launch_bounds__(256) void topk_kernel()
{
    __shared__ float v[256];
    __shared__ int   id[256];
    __shared__ unsigned char sel[196];
    int b = blockIdx.x, t = threadIdx.x;
    v[t]  = (t < 196) ? g_cls[b*196 + t] : -3.0e38f;
    id[t] = t;
    __syncthreads();
    for (int k=2;k<=256;k<<=1){
        for (int j=k>>1;j>0;j>>=1){
            int ixj = t ^ j;
            if (ixj > t){
                float va=v[t], vb=v[ixj];
                int   ia=id[t], ib=id[ixj];
                bool aWorse = (va < vb) || (va == vb && ia > ib);
                bool dirDesc = ((t & k) == 0);
                bool doswap = dirDesc ? aWorse : !aWorse;
                if (doswap){ v[t]=vb; v[ixj]=va; id[t]=ib; id[ixj]=ia; }
            }
            __syncthreads();
        }
    }
    if (t < LEFT) g_idx[b*LEFT + t] = id[t];
    if (t < 196) sel[t] = 0;
    __syncthreads();
    if (t < LEFT) sel[id[t]] = 1;
    __syncthreads();
    if (t == 0){
        int c = 0;
        for (int j=0;j<196;j++) if (!sel[j]) g_cmp[b*CMPL + (c++)] = j;
    }
}

/* ---------------- gathers (padded for the distance GEMM) ---------------- */
__global__ __launch_bounds__(256) void gather_xo_kernel()
{
    int l = blockIdx.x, b = blockIdx.y, t = threadIdx.x;
    float* dst = g_XO + ((size_t)b*144 + l)*Cx;
    float ss = 0.f;
    if (l < LEFT){
        int j = g_idx[b*LEFT + l];
        const float* src = g_x1 + ((size_t)(b*Nx) + 1 + j)*Cx;
        #pragma unroll
        for (int r=0;r<3;r++){
            float vv = src[t + r*256];
            dst[t + r*256] = vv;
            ss += vv*vv;
        }
    } else {
        #pragma unroll
        for (int r=0;r<3;r++) dst[t + r*256] = 0.f;
    }
    __shared__ float sr[8];
    #pragma unroll
    for (int o=16;o;o>>=1) ss += __shfl_xor_sync(0xffffffffu, ss, o);
    if ((t&31)==0) sr[t>>5] = ss;
    __syncthreads();
    if (t == 0 && l < LEFT){
        float tot = 0.f;
        #pragma unroll
        for (int i=0;i<8;i++) tot += sr[i];
        g_nrm[b*LEFT + l] = sqrtf(tot);
    }
}

__global__ __launch_bounds__(256) void gather_nt_kernel()
{
    int m = blockIdx.x, b = blockIdx.y, t = threadIdx.x;
    float* dst = g_NT + ((size_t)b*64 + m)*Cx;
    if (m < CMPL){
        int j = g_cmp[b*CMPL + m];
        const float* src = g_x1 + ((size_t)(b*Nx) + 1 + j)*Cx;
        #pragma unroll
        for (int r=0;r<3;r++) dst[t + r*256] = src[t + r*256];
    } else {
        #pragma unroll
        for (int r=0;r<3;r++) dst[t + r*256] = 0.f;
    }
}

/* ---------------- distance GEMM: per batch, D[64pad,144pad] = NT @ XO^T ---- */
__global__ __launch_bounds__(256) void dist_kernel()
{
    __shared__ float NTs[64*33];
    __shared__ float XOs[144*33];
    int b = blockIdx.x, tid = threadIdx.x;
    int tx = tid & 15, ty = tid >> 4;
    const float* NTb = g_NT + (size_t)b*64*Cx;
    const float* XOb = g_XO + (size_t)b*144*Cx;
    float acc[4][9];
    #pragma unroll
    for (int i=0;i<4;i++)
        #pragma unroll
        for (int j=0;j<9;j++) acc[i][j]=0.f;

    for (int k0=0;k0<Cx;k0+=32){
        for (int i=tid;i<64*32;i+=256){ int m=i>>5, kk=i&31; NTs[m*33+kk]=NTb[(size_t)m*Cx+k0+kk]; }
        for (int i=tid;i<144*32;i+=256){ int l=i>>5, kk=i&31; XOs[l*33+kk]=XOb[(size_t)l*Cx+k0+kk]; }
        __syncthreads();
        #pragma unroll 8
        for (int kk=0;kk<32;kk++){
            float a[4], bb2[9];
            #pragma unroll
            for (int ii=0;ii<4;ii++) a[ii]  = NTs[(ty*4+ii)*33 + kk];
            #pragma unroll
            for (int jj=0;jj<9;jj++) bb2[jj]= XOs[(tx*9+jj)*33 + kk];
            #pragma unroll
            for (int ii=0;ii<4;ii++)
                #pragma unroll
                for (int jj=0;jj<9;jj++)
                    acc[ii][jj] = fmaf(a[ii], bb2[jj], acc[ii][jj]);
        }
        __syncthreads();
    }
    #pragma unroll
    for (int ii=0;ii<4;ii++)
        #pragma unroll
        for (int jj=0;jj<9;jj++)
            g_D[(size_t)b*9216 + (ty*4+ii)*144 + (tx*9+jj)] = acc[ii][jj];
}

/* ---------------- argmax over topk (first-max tie rule, matches jnp) ------- */
__global__ void argmax_kernel()
{
    int m = blockIdx.x, b = blockIdx.y, lane = threadIdx.x;
    const float* Dr = g_D + (size_t)b*9216 + m*144;
    float best = -3.0e38f; int bi = 1<<30;
    for (int l=lane; l<LEFT; l+=32){
        float v = Dr[l] / g_nrm[b*LEFT + l];
        if (v > best || (v == best && l < bi)){ best = v; bi = l; }
    }
    #pragma unroll
    for (int o=16;o;o>>=1){
        float v2 = __shfl_xor_sync(0xffffffffu, best, o);
        int   i2 = __shfl_xor_sync(0xffffffffu, bi,   o);
        if (v2 > best || (v2 == best && i2 < bi)){ best = v2; bi = i2; }
    }
    if (lane == 0) g_node[b*CMPL + m] = bi;
}

/* ---------------- deterministic merge (no atomics): one block per (l,b) ---- */
__global__ __launch_bounds__(256) void merge_kernel()
{
    int l = blockIdx.x, b = blockIdx.y, t = threadIdx.x;
    int jt = g_idx[b*LEFT + l];
    float w = g_cls[b*196 + jt];
    const float* src = g_x1 + ((size_t)(b*Nx) + 1 + jt)*Cx;
    float a0 = src[t]*w, a1 = src[t+256]*w, a2 = src[t+512]*w;
    float tka = w;
    for (int m=0;m<CMPL;m++){
        if (g_node[b*CMPL + m] == l){
            int jm = g_cmp[b*CMPL + m];
            float wm = g_cls[b*196 + jm];
            const float* s2 = g_x1 + ((size_t)(b*Nx) + 1 + jm)*Cx;
            a0 += s2[t]*wm; a1 += s2[t+256]*wm; a2 += s2[t+512]*wm;
            tka += wm;
        }
    }
    float* dst = g_xm + ((size_t)(b*NM) + 1 + l)*Cx;
    dst[t]     = a0 / tka;
    dst[t+256] = a1 / tka;
    dst[t+512] = a2 / tka;
}

__global__ void copy_cls_kernel()
{
    int b = blockIdx.x, t = threadIdx.x;
    const float* s = g_x1 + (size_t)b*Nx*Cx;
    float* d = g_xm + (size_t)b*NM*Cx;
    #pragma unroll
    for (int r=0;r<3;r++) d[t + r*256] = s[t + r*256];
}

/* ---------------- host launcher ---------------- */
extern "C" void kernel_launch(void* const* d_in, const int* in_sizes, int n_in,
                              void* d_out, int out_size)
{
    const float* x     = (const float*)d_in[0];
    const float* n1w   = (const float*)d_in[1];
    const float* n1b   = (const float*)d_in[2];
    const float* qkvw  = (const float*)d_in[3];
    const float* projw = (const float*)d_in[4];
    const float* projb = (const float*)d_in[5];
    const float* n2w   = (const float*)d_in[6];
    const float* n2b   = (const float*)d_in[7];
    const float* fc1w  = (const float*)d_in[8];
    const float* fc1b  = (const float*)d_in[9];
    const float* fc2w  = (const float*)d_in[10];
    const float* fc2b  = (const float*)d_in[11];
    float* out = (float*)d_out;

    void *p;
    cudaGetSymbolAddress(&p, g_xn);   float* pxn  = (float*)p;
    cudaGetSymbolAddress(&p, g_qkv);  float* pqkv = (float*)p;
    cudaGetSymbolAddress(&p, g_ao);   float* pao  = (float*)p;
    cudaGetSymbolAddress(&p, g_x1);   float* px1  = (float*)p;
    cudaGetSymbolAddress(&p, g_clsh); float* pclsh= (float*)p;
    cudaGetSymbolAddress(&p, g_xm);   float* pxm  = (float*)p;
    cudaGetSymbolAddress(&p, g_xn2);  float* pxn2 = (float*)p;
    cudaGetSymbolAddress(&p, g_h1);   float* ph1  = (float*)p;

    /* 1) LN1 */
    ln_kernel<<<NROWS, 256>>>(x, n1w, n1b, pxn);

    /* 2) QKV GEMM: [25216,768] x [768,2304]  (fp32 — feeds top-k selection) */
    sgemm<0><<<dim3(2304/128, NROWS/128), 256>>>(pxn, qkvw, nullptr, nullptr, pqkv,
                                                 NROWS, 2304, Cx);

    /* 3) attention per (head, batch) */
    cudaFuncSetAttribute(attn_kernel, cudaFuncAttributeMaxDynamicSharedMemorySize,
                         SMEM_ATTN_FLOATS*4);
    attn_kernel<<<dim3(Hx, Bx), 256, SMEM_ATTN_FLOATS*4>>>(pqkv, pao, pclsh);

    /* 4) proj GEMM + bias + residual(x) -> x1 (fp32 — feeds argmax selection) */
    sgemm<2><<<dim3(Cx/128, NROWS/128), 256>>>(pao, projw, projb, x, px1,
                                               NROWS, Cx, Cx);

    /* 5) cls attention mean over heads, 6) top-k + complement */
    cls_mean_kernel<<<Bx, 256>>>();
    topk_kernel<<<Bx, 256>>>();

    /* 7) gathers + norms, 8) cosine distance GEMM, 9) argmax */
    gather_xo_kernel<<<dim3(144, Bx), 256>>>();
    gather_nt_kernel<<<dim3(64, Bx), 256>>>();
    dist_kernel<<<Bx, 256>>>();
    argmax_kernel<<<dim3(CMPL, Bx), 32>>>();

    /* 10) deterministic merge + cls copy -> xm */
    merge_kernel<<<dim3(LEFT, Bx), 256>>>();
    copy_cls_kernel<<<Bx, 256>>>();

    /* 11) LN2, 12) fc1+GELU (tf32 TC v2), 13) fc2+bias+residual (tf32 TC v2) */
    ln_kernel<<<M2, 256>>>(pxm, n2w, n2b, pxn2);
    mma_gemm<3><<<dim3(FF/128, M2/128), 256>>>(pxn2, fc1w, fc1b, nullptr, ph1,
                                               M2, FF, Cx);
    mma_gemm<2><<<dim3(Cx/128, M2/128), 256>>>(ph1, fc2w, fc2b, pxm, out,
                                               M2, Cx, FF);
    (void)in_sizes; (void)n_in; (void)out_size;
}

// round 7
// speedup vs baseline: 1.5143x; 1.0389x over previous
#include <cuda_runtime.h>
#include <math.h>
#include <stdint.h>

#define Bx   128
#define Nx   197
#define Cx   768
#define Hx   12
#define Dx   64
#define NROWS 25216      /* Bx*Nx */
#define LEFT 138
#define CMPL 58
#define NM   139
#define M2   17792       /* Bx*NM */
#define FF   3072

/* ---------------- device scratch (no allocations allowed) ---------------- */
__device__ float g_xn [NROWS*Cx];
__device__ float g_qkv[NROWS*3*Cx];
__device__ float g_ao [NROWS*Cx];
__device__ float g_x1 [NROWS*Cx];
__device__ float g_clsh[Bx*Hx*196];
__device__ float g_cls[Bx*196];
__device__ int   g_idx[Bx*LEFT];
__device__ int   g_cmp[Bx*CMPL];
__device__ float g_NT[Bx*64*Cx];
__device__ float g_XO[Bx*144*Cx];
__device__ float g_nrm[Bx*LEFT];
__device__ float g_D[Bx*64*144];
__device__ int   g_node[Bx*CMPL];
__device__ float g_xm [M2*Cx];
__device__ float g_xn2[M2*Cx];
__device__ float g_h1 [M2*FF];

/* ---------------- cp.async helpers ---------------- */
__device__ __forceinline__ void cpasync16(uint32_t d, const void* s){
    asm volatile("cp.async.cg.shared.global [%0], [%1], 16;" :: "r"(d), "l"(s));
}
__device__ __forceinline__ void cp_commit(){ asm volatile("cp.async.commit_group;"); }
__device__ __forceinline__ void cp_wait0(){ asm volatile("cp.async.wait_group 0;"); }

/* ---------------- LayerNorm: one block per row, 256 thr, C=768 ---------------- */
__global__ __launch_bounds__(256) void ln_kernel(const float* __restrict__ x,
                                                 const float* __restrict__ w,
                                                 const float* __restrict__ bb,
                                                 float* __restrict__ y)
{
    int row = blockIdx.x;
    const float* xr = x + (size_t)row * Cx;
    float* yr = y + (size_t)row * Cx;
    int t = threadIdx.x;
    float v0 = xr[t], v1 = xr[t+256], v2 = xr[t+512];
    float s = v0+v1+v2;
    float q = v0*v0 + v1*v1 + v2*v2;
    __shared__ float sred[16];
    #pragma unroll
    for (int o=16;o;o>>=1){ s += __shfl_xor_sync(0xffffffffu,s,o); q += __shfl_xor_sync(0xffffffffu,q,o); }
    if ((t&31)==0){ sred[t>>5] = s; sred[8+(t>>5)] = q; }
    __syncthreads();
    s = 0.f; q = 0.f;
    #pragma unroll
    for (int i=0;i<8;i++){ s += sred[i]; q += sred[8+i]; }
    float mean = s * (1.0f/768.0f);
    float var  = q * (1.0f/768.0f) - mean*mean;
    float rstd = rsqrtf(var + 1e-5f);
    yr[t]     = (v0-mean)*rstd*w[t]     + bb[t];
    yr[t+256] = (v1-mean)*rstd*w[t+256] + bb[t+256];
    yr[t+512] = (v2-mean)*rstd*w[t+512] + bb[t+512];
}

/* ---------------- SGEMM 128x128x8, 256 thr, 8x8/thread, fp32 ----------------
   v3: conflict-free B-fragment mapping (cols {tx*4..+3} and {64+tx*4..+3});
   bit-exact vs R1 per output element. regs ~128, 2 CTAs/SM.
   EPI: 0 = none, 1 = +bias, 2 = +bias+residual, 3 = +bias+exact GELU        */
template<int EPI>
__global__ __launch_bounds__(256) void sgemm(const float* __restrict__ A,
                                             const float* __restrict__ B,
                                             const float* __restrict__ bias,
                                             const float* __restrict__ res,
                                             float* __restrict__ C,
                                             int M, int N, int K)
{
    __shared__ float As[8][128];
    __shared__ float Bs[8][128];
    int tid = threadIdx.x;
    int bm = blockIdx.y << 7, bn = blockIdx.x << 7;
    const float* Ap = A + (size_t)(bm + (tid>>1))*K + ((tid&1)<<2);
    const float* Bp = B + (size_t)(tid>>5)*N + bn + ((tid&31)<<2);
    int tx = tid & 15, ty = tid >> 4;
    int arow = tid>>1, ac = (tid&1)<<2;
    int brow = tid>>5, bc = (tid&31)<<2;
    float acc[8][8];
    #pragma unroll
    for (int i=0;i<8;i++)
        #pragma unroll
        for (int j=0;j<8;j++) acc[i][j] = 0.f;

    for (int k0=0;k0<K;k0+=8){
        float4 av = *(const float4*)Ap; Ap += 8;
        float4 bv = *(const float4*)Bp; Bp += (size_t)8*N;
        As[ac+0][arow]=av.x; As[ac+1][arow]=av.y; As[ac+2][arow]=av.z; As[ac+3][arow]=av.w;
        *(float4*)&Bs[brow][bc] = bv;
        __syncthreads();
        #pragma unroll
        for (int kk=0;kk<8;kk++){
            float a[8], b[8];
            *(float4*)(a)   = *(const float4*)&As[kk][ty<<3];
            *(float4*)(a+4) = *(const float4*)&As[kk][(ty<<3)+4];
            *(float4*)(b)   = *(const float4*)&Bs[kk][tx<<2];         /* cols tx*4..+3   */
            *(float4*)(b+4) = *(const float4*)&Bs[kk][64+(tx<<2)];    /* cols 64+tx*4..+3 */
            #pragma unroll
            for (int i=0;i<8;i++)
                #pragma unroll
                for (int j=0;j<8;j++)
                    acc[i][j] = fmaf(a[i], b[j], acc[i][j]);
        }
        __syncthreads();
    }
    /* epilogue: rows bm+ty*8+i, col groups {bn+tx*4, bn+64+tx*4} */
    #pragma unroll
    for (int i=0;i<8;i++){
        int row = bm + (ty<<3) + i;
        #pragma unroll
        for (int half=0;half<2;half++){
            int col = bn + (half<<6) + (tx<<2);
            size_t off = (size_t)row*N + col;
            float4 v;
            v.x = acc[i][half*4+0];
            v.y = acc[i][half*4+1];
            v.z = acc[i][half*4+2];
            v.w = acc[i][half*4+3];
            if (EPI >= 1){
                float4 bb4 = *(const float4*)&bias[col];
                v.x += bb4.x; v.y += bb4.y; v.z += bb4.z; v.w += bb4.w;
            }
            if (EPI == 2){
                float4 r4 = *(const float4*)&res[off];
                v.x += r4.x; v.y += r4.y; v.z += r4.z; v.w += r4.w;
            }
            if (EPI == 3){
                v.x = 0.5f*v.x*(1.0f + erff(v.x*0.70710678118654752f));
                v.y = 0.5f*v.y*(1.0f + erff(v.y*0.70710678118654752f));
                v.z = 0.5f*v.z*(1.0f + erff(v.z*0.70710678118654752f));
                v.w = 0.5f*v.w*(1.0f + erff(v.w*0.70710678118654752f));
            }
            *(float4*)(C + off) = v;
        }
    }
}

/* ---------------- TF32 tensor-core GEMM v2 (mma.sync m16n8k8) --------------
   128x128x16 tile, 256 thr (8 warps, 2x4 warp grid, 64x32 warp tiles).
   cp.async staging, raw-fp32-bit tf32 feed, 2 CTAs/SM.
   EPI: 2 = +bias+residual, 3 = +bias+exact GELU. M%128==0, N%128==0, K%16==0 */
template<int EPI>
__global__ __launch_bounds__(256, 2) void mma_gemm(const float* __restrict__ A,
                                                   const float* __restrict__ B,
                                                   const float* __restrict__ bias,
                                                   const float* __restrict__ res,
                                                   float* __restrict__ C,
                                                   int M, int N, int K)
{
    __shared__ float As[2][128][20];   /* padded: frag LDS conflict-free */
    __shared__ float Bs[2][16][136];

    int tid = threadIdx.x;
    int bm = blockIdx.y << 7, bn = blockIdx.x << 7;
    int lane = tid & 31, warp = tid >> 5;
    int wm = (warp >> 2) << 6;         /* 0 or 64  */
    int wn = (warp & 3) << 5;          /* 0,32,64,96 */
    int gq = lane >> 2, gr = lane & 3;

    int ar = tid >> 1, ac = (tid & 1) << 3;
    int br = tid >> 4, bc = (tid & 15) << 3;
    const float* Ag = A + (size_t)(bm + ar)*K + ac;
    const float* Bg = B + (size_t)br*N + bn + bc;

    uint32_t sA = (uint32_t)__cvta_generic_to_shared(&As[0][0][0]);
    uint32_t sB = (uint32_t)__cvta_generic_to_shared(&Bs[0][0][0]);
    uint32_t aDst0 = sA + (uint32_t)(ar*80 + ac*4);
    uint32_t bDst0 = sB + (uint32_t)(br*544 + bc*4);
    const uint32_t A_BUF = 128*20*4, B_BUF = 16*136*4;

    float acc[4][4][4];
    #pragma unroll
    for (int mi=0;mi<4;mi++)
        #pragma unroll
        for (int ni=0;ni<4;ni++)
            #pragma unroll
            for (int r=0;r<4;r++) acc[mi][ni][r] = 0.f;

    /* prologue: stage tile 0 */
    cpasync16(aDst0,      Ag);
    cpasync16(aDst0 + 16, Ag + 4);
    cpasync16(bDst0,      Bg);
    cpasync16(bDst0 + 16, Bg + 4);
    cp_commit();

    int KT = K >> 4;
    for (int kt = 0; kt < KT; kt++){
        int cur = kt & 1;
        cp_wait0();
        __syncthreads();
        if (kt < KT-1){
            int nxt = cur ^ 1;
            const float* Ag2 = Ag + ((kt+1) << 4);
            const float* Bg2 = Bg + (size_t)((kt+1) << 4) * N;
            uint32_t ad = aDst0 + (uint32_t)nxt * A_BUF;
            uint32_t bd = bDst0 + (uint32_t)nxt * B_BUF;
            cpasync16(ad,      Ag2);
            cpasync16(ad + 16, Ag2 + 4);
            cpasync16(bd,      Bg2);
            cpasync16(bd + 16, Bg2 + 4);
            cp_commit();
        }
        #pragma unroll
        for (int ks = 0; ks < 16; ks += 8){
            uint32_t Af[4][4], Bf[4][2];
            #pragma unroll
            for (int mi=0;mi<4;mi++){
                int m0 = wm + (mi<<4) + gq;
                Af[mi][0] = __float_as_uint(As[cur][m0  ][ks+gr]);
                Af[mi][1] = __float_as_uint(As[cur][m0+8][ks+gr]);
                Af[mi][2] = __float_as_uint(As[cur][m0  ][ks+4+gr]);
                Af[mi][3] = __float_as_uint(As[cur][m0+8][ks+4+gr]);
            }
            #pragma unroll
            for (int ni=0;ni<4;ni++){
                int n0 = wn + (ni<<3) + gq;
                Bf[ni][0] = __float_as_uint(Bs[cur][ks+gr  ][n0]);
                Bf[ni][1] = __float_as_uint(Bs[cur][ks+4+gr][n0]);
            }
            #pragma unroll
            for (int mi=0;mi<4;mi++)
                #pragma unroll
                for (int ni=0;ni<4;ni++){
                    asm volatile(
                        "mma.sync.aligned.m16n8k8.row.col.f32.tf32.tf32.f32 "
                        "{%0,%1,%2,%3}, {%4,%5,%6,%7}, {%8,%9}, {%0,%1,%2,%3};"
                        : "+f"(acc[mi][ni][0]), "+f"(acc[mi][ni][1]),
                          "+f"(acc[mi][ni][2]), "+f"(acc[mi][ni][3])
                        : "r"(Af[mi][0]), "r"(Af[mi][1]), "r"(Af[mi][2]), "r"(Af[mi][3]),
                          "r"(Bf[ni][0]), "r"(Bf[ni][1]));
                }
        }
    }

    /* epilogue */
    #pragma unroll
    for (int mi=0;mi<4;mi++){
        int row = bm + wm + (mi<<4) + gq;
        #pragma unroll
        for (int ni=0;ni<4;ni++){
            int col = bn + wn + (ni<<3) + (gr<<1);
            float b0 = bias[col], b1 = bias[col+1];
            size_t o0 = (size_t)row*N + col;
            size_t o1 = (size_t)(row+8)*N + col;
            float v00 = acc[mi][ni][0] + b0;
            float v01 = acc[mi][ni][1] + b1;
            float v10 = acc[mi][ni][2] + b0;
            float v11 = acc[mi][ni][3] + b1;
            if (EPI == 2){
                v00 += res[o0];   v01 += res[o0+1];
                v10 += res[o1];   v11 += res[o1+1];
            }
            if (EPI == 3){
                v00 = 0.5f*v00*(1.0f + erff(v00*0.70710678118654752f));
                v01 = 0.5f*v01*(1.0f + erff(v01*0.70710678118654752f));
                v10 = 0.5f*v10*(1.0f + erff(v10*0.70710678118654752f));
                v11 = 0.5f*v11*(1.0f + erff(v11*0.70710678118654752f));
            }
            float2 w0; w0.x = v00; w0.y = v01;
            float2 w1; w1.x = v10; w1.y = v11;
            *(float2*)(C + o0) = w0;
            *(float2*)(C + o1) = w1;
        }
    }
}

/* ---------------- Attention: one block per (head, batch) ----------------
   Q,K,V (197x64 fp32 each, padded to 65 cols) + per-warp prob rows in smem */
#define QKV_PAD 65
#define QKV_SZ  (Nx*QKV_PAD)            /* 12805 */
#define SMEM_ATTN_FLOATS (3*QKV_SZ + 8*200)
__global__ __launch_bounds__(256) void attn_kernel(const float* __restrict__ qkv,
                                                   float* __restrict__ out,
                                                   float* __restrict__ clsh)
{
    extern __shared__ float sm[];
    float* Qs = sm;
    float* Ks = sm + QKV_SZ;
    float* Vs = sm + 2*QKV_SZ;
    float* Pb = sm + 3*QKV_SZ;
    int h = blockIdx.x, b = blockIdx.y;
    int tid = threadIdx.x, warp = tid>>5, lane = tid&31;

    const float* base = qkv + (size_t)b*Nx*2304 + h*64;
    for (int i = tid; i < Nx*64; i += 256){
        int n = i>>6, c = i&63;
        size_t s = (size_t)n*2304 + c;
        Qs[n*QKV_PAD+c] = base[s];
        Ks[n*QKV_PAD+c] = base[s+768];
        Vs[n*QKV_PAD+c] = base[s+1536];
    }
    __syncthreads();

    float* pb = Pb + warp*200;
    for (int i = warp; i < Nx; i += 8){
        const float* qr = Qs + i*QKV_PAD;
        float sc[7];
        int joff[7];
        #pragma unroll
        for (int t=0;t<7;t++){ sc[t]=0.f; int j=lane+32*t; joff[t] = (j<Nx ? j : 0)*QKV_PAD; }
        #pragma unroll 4
        for (int c=0;c<64;c++){
            float qc = qr[c];
            #pragma unroll
            for (int t=0;t<7;t++) sc[t] = fmaf(qc, Ks[joff[t]+c], sc[t]);
        }
        float mx = -3.0e38f;
        #pragma unroll
        for (int t=0;t<7;t++){
            int j=lane+32*t;
            sc[t] = (j<Nx) ? sc[t]*0.125f : -3.0e38f;
            mx = fmaxf(mx, sc[t]);
        }
        #pragma unroll
        for (int o=16;o;o>>=1) mx = fmaxf(mx, __shfl_xor_sync(0xffffffffu, mx, o));
        float sum = 0.f;
        #pragma unroll
        for (int t=0;t<7;t++){
            int j=lane+32*t;
            float e = (j<Nx) ? expf(sc[t]-mx) : 0.f;
            sc[t]=e; sum+=e;
        }
        #pragma unroll
        for (int o=16;o;o>>=1) sum += __shfl_xor_sync(0xffffffffu, sum, o);
        float inv = 1.0f/sum;
        #pragma unroll
        for (int t=0;t<7;t++){
            int j=lane+32*t;
            if (j<Nx) pb[j] = sc[t]*inv;
        }
        __syncwarp();
        if (i == 0){
            #pragma unroll
            for (int t=0;t<7;t++){
                int j=lane+32*t;
                if (j>=1 && j<Nx) clsh[((size_t)b*Hx + h)*196 + (j-1)] = sc[t]*inv;
            }
        }
        float o0=0.f, o1=0.f;
        for (int j=0;j<Nx;j++){
            float p = pb[j];
            o0 = fmaf(p, Vs[j*QKV_PAD+lane], o0);
            o1 = fmaf(p, Vs[j*QKV_PAD+lane+32], o1);
        }
        size_t oo = (size_t)(b*Nx + i)*Cx + h*64;
        out[oo + lane]      = o0;
        out[oo + lane + 32] = o1;
        __syncwarp();
    }
}

/* ---------------- cls_attn = mean over heads (deterministic) ---------------- */
__global__ void cls_mean_kernel()
{
    int b = blockIdx.x, j = threadIdx.x;
    if (j < 196){
        float s = 0.f;
        #pragma unroll
        for (int h=0; h<Hx; h++) s += g_clsh[((size_t)b*Hx + h)*196 + j];
        g_cls[b*196 + j] = s * (1.0f/12.0f);
    }
}

/* ---------------- top-k (138 of 196) via bitonic sort + complement --------- */
__global__ __launch_bounds__(256) void topk_kernel()
{
    __shared__ float v[256];
    __shared__ int   id[256];
    __shared__ unsigned char sel[196];
    int b = blockIdx.x, t = threadIdx.x;
    v[t]  = (t < 196) ? g_cls[b*196 + t] : -3.0e38f;
    id[t] = t;
    __syncthreads();
    for (int k=2;k<=256;k<<=1){
        for (int j=k>>1;j>0;j>>=1){
            int ixj = t ^ j;
            if (ixj > t){
                float va=v[t], vb=v[ixj];
                int   ia=id[t], ib=id[ixj];
                bool aWorse = (va < vb) || (va == vb && ia > ib);
                bool dirDesc = ((t & k) == 0);
                bool doswap = dirDesc ? aWorse : !aWorse;
                if (doswap){ v[t]=vb; v[ixj]=va; id[t]=ib; id[ixj]=ia; }
            }
            __syncthreads();
        }
    }
    if (t < LEFT) g_idx[b*LEFT + t] = id[t];
    if (t < 196) sel[t] = 0;
    __syncthreads();
    if (t < LEFT) sel[id[t]] = 1;
    __syncthreads();
    if (t == 0){
        int c = 0;
        for (int j=0;j<196;j++) if (!sel[j]) g_cmp[b*CMPL + (c++)] = j;
    }
}

/* ---------------- gathers (padded for the distance GEMM) ---------------- */
__global__ __launch_bounds__(256) void gather_xo_kernel()
{
    int l = blockIdx.x, b = blockIdx.y, t = threadIdx.x;
    float* dst = g_XO + ((size_t)b*144 + l)*Cx;
    float ss = 0.f;
    if (l < LEFT){
        int j = g_idx[b*LEFT + l];
        const float* src = g_x1 + ((size_t)(b*Nx) + 1 + j)*Cx;
        #pragma unroll
        for (int r=0;r<3;r++){
            float vv = src[t + r*256];
            dst[t + r*256] = vv;
            ss += vv*vv;
        }
    } else {
        #pragma unroll
        for (int r=0;r<3;r++) dst[t + r*256] = 0.f;
    }
    __shared__ float sr[8];
    #pragma unroll
    for (int o=16;o;o>>=1) ss += __shfl_xor_sync(0xffffffffu, ss, o);
    if ((t&31)==0) sr[t>>5] = ss;
    __syncthreads();
    if (t == 0 && l < LEFT){
        float tot = 0.f;
        #pragma unroll
        for (int i=0;i<8;i++) tot += sr[i];
        g_nrm[b*LEFT + l] = sqrtf(tot);
    }
}

__global__ __launch_bounds__(256) void gather_nt_kernel()
{
    int m = blockIdx.x, b = blockIdx.y, t = threadIdx.x;
    float* dst = g_NT + ((size_t)b*64 + m)*Cx;
    if (m < CMPL){
        int j = g_cmp[b*CMPL + m];
        const float* src = g_x1 + ((size_t)(b*Nx) + 1 + j)*Cx;
        #pragma unroll
        for (int r=0;r<3;r++) dst[t + r*256] = src[t + r*256];
    } else {
        #pragma unroll
        for (int r=0;r<3;r++) dst[t + r*256] = 0.f;
    }
}

/* ---------------- distance GEMM: per batch, D[64pad,144pad] = NT @ XO^T ---- */
__global__ __launch_bounds__(256) void dist_kernel()
{
    __shared__ float NTs[64*33];
    __shared__ float XOs[144*33];
    int b = blockIdx.x, tid = threadIdx.x;
    int tx = tid & 15, ty = tid >> 4;
    const float* NTb = g_NT + (size_t)b*64*Cx;
    const float* XOb = g_XO + (size_t)b*144*Cx;
    float acc[4][9];
    #pragma unroll
    for (int i=0;i<4;i++)
        #pragma unroll
        for (int j=0;j<9;j++) acc[i][j]=0.f;

    for (int k0=0;k0<Cx;k0+=32){
        for (int i=tid;i<64*32;i+=256){ int m=i>>5, kk=i&31; NTs[m*33+kk]=NTb[(size_t)m*Cx+k0+kk]; }
        for (int i=tid;i<144*32;i+=256){ int l=i>>5, kk=i&31; XOs[l*33+kk]=XOb[(size_t)l*Cx+k0+kk]; }
        __syncthreads();
        #pragma unroll 8
        for (int kk=0;kk<32;kk++){
            float a[4], bb2[9];
            #pragma unroll
            for (int ii=0;ii<4;ii++) a[ii]  = NTs[(ty*4+ii)*33 + kk];
            #pragma unroll
            for (int jj=0;jj<9;jj++) bb2[jj]= XOs[(tx*9+jj)*33 + kk];
            #pragma unroll
            for (int ii=0;ii<4;ii++)
                #pragma unroll
                for (int jj=0;jj<9;jj++)
                    acc[ii][jj] = fmaf(a[ii], bb2[jj], acc[ii][jj]);
        }
        __syncthreads();
    }
    #pragma unroll
    for (int ii=0;ii<4;ii++)
        #pragma unroll
        for (int jj=0;jj<9;jj++)
            g_D[(size_t)b*9216 + (ty*4+ii)*144 + (tx*9+jj)] = acc[ii][jj];
}

/* ---------------- argmax over topk (first-max tie rule, matches jnp) ------- */
__global__ void argmax_kernel()
{
    int m = blockIdx.x, b = blockIdx.y, lane = threadIdx.x;
    const float* Dr = g_D + (size_t)b*9216 + m*144;
    float best = -3.0e38f; int bi = 1<<30;
    for (int l=lane; l<LEFT; l+=32){
        float v = Dr[l] / g_nrm[b*LEFT + l];
        if (v > best || (v == best && l < bi)){ best = v; bi = l; }
    }
    #pragma unroll
    for (int o=16;o;o>>=1){
        float v2 = __shfl_xor_sync(0xffffffffu, best, o);
        int   i2 = __shfl_xor_sync(0xffffffffu, bi,   o);
        if (v2 > best || (v2 == best && i2 < bi)){ best = v2; bi = i2; }
    }
    if (lane == 0) g_node[b*CMPL + m] = bi;
}

/* ---------------- deterministic merge (no atomics): one block per (l,b) ---- */
__global__ __launch_bounds__(256) void merge_kernel()
{
    int l = blockIdx.x, b = blockIdx.y, t = threadIdx.x;
    int jt = g_idx[b*LEFT + l];
    float w = g_cls[b*196 + jt];
    const float* src = g_x1 + ((size_t)(b*Nx) + 1 + jt)*Cx;
    float a0 = src[t]*w, a1 = src[t+256]*w, a2 = src[t+512]*w;
    float tka = w;
    for (int m=0;m<CMPL;m++){
        if (g_node[b*CMPL + m] == l){
            int jm = g_cmp[b*CMPL + m];
            float wm = g_cls[b*196 + jm];
            const float* s2 = g_x1 + ((size_t)(b*Nx) + 1 + jm)*Cx;
            a0 += s2[t]*wm; a1 += s2[t+256]*wm; a2 += s2[t+512]*wm;
            tka += wm;
        }
    }
    float* dst = g_xm + ((size_t)(b*NM) + 1 + l)*Cx;
    dst[t]     = a0 / tka;
    dst[t+256] = a1 / tka;
    dst[t+512] = a2 / tka;
}

__global__ void copy_cls_kernel()
{
    int b = blockIdx.x, t = threadIdx.x;
    const float* s = g_x1 + (size_t)b*Nx*Cx;
    float* d = g_xm + (size_t)b*NM*Cx;
    #pragma unroll
    for (int r=0;r<3;r++) d[t + r*256] = s[t + r*256];
}

/* ---------------- host launcher ---------------- */
extern "C" void kernel_launch(void* const* d_in, const int* in_sizes, int n_in,
                              void* d_out, int out_size)
{
    const float* x     = (const float*)d_in[0];
    const float* n1w   = (const float*)d_in[1];
    const float* n1b   = (const float*)d_in[2];
    const float* qkvw  = (const float*)d_in[3];
    const float* projw = (const float*)d_in[4];
    const float* projb = (const float*)d_in[5];
    const float* n2w   = (const float*)d_in[6];
    const float* n2b   = (const float*)d_in[7];
    const float* fc1w  = (const float*)d_in[8];
    const float* fc1b  = (const float*)d_in[9];
    const float* fc2w  = (const float*)d_in[10];
    const float* fc2b  = (const float*)d_in[11];
    float* out = (float*)d_out;

    void *p;
    cudaGetSymbolAddress(&p, g_xn);   float* pxn  = (float*)p;
    cudaGetSymbolAddress(&p, g_qkv);  float* pqkv = (float*)p;
    cudaGetSymbolAddress(&p, g_ao);   float* pao  = (float*)p;
    cudaGetSymbolAddress(&p, g_x1);   float* px1  = (float*)p;
    cudaGetSymbolAddress(&p, g_clsh); float* pclsh= (float*)p;
    cudaGetSymbolAddress(&p, g_xm);   float* pxm  = (float*)p;
    cudaGetSymbolAddress(&p, g_xn2);  float* pxn2 = (float*)p;
    cudaGetSymbolAddress(&p, g_h1);   float* ph1  = (float*)p;

    /* 1) LN1 */
    ln_kernel<<<NROWS, 256>>>(x, n1w, n1b, pxn);

    /* 2) QKV GEMM: [25216,768] x [768,2304]  (fp32 — feeds top-k selection) */
    sgemm<0><<<dim3(2304/128, NROWS/128), 256>>>(pxn, qkvw, nullptr, nullptr, pqkv,
                                                 NROWS, 2304, Cx);

    /* 3) attention per (head, batch) */
    cudaFuncSetAttribute(attn_kernel, cudaFuncAttributeMaxDynamicSharedMemorySize,
                         SMEM_ATTN_FLOATS*4);
    attn_kernel<<<dim3(Hx, Bx), 256, SMEM_ATTN_FLOATS*4>>>(pqkv, pao, pclsh);

    /* 4) proj GEMM + bias + residual(x) -> x1 (fp32 — feeds argmax selection) */
    sgemm<2><<<dim3(Cx/128, NROWS/128), 256>>>(pao, projw, projb, x, px1,
                                               NROWS, Cx, Cx);

    /* 5) cls attention mean over heads, 6) top-k + complement */
    cls_mean_kernel<<<Bx, 256>>>();
    topk_kernel<<<Bx, 256>>>();

    /* 7) gathers + norms, 8) cosine distance GEMM, 9) argmax */
    gather_xo_kernel<<<dim3(144, Bx), 256>>>();
    gather_nt_kernel<<<dim3(64, Bx), 256>>>();
    dist_kernel<<<Bx, 256>>>();
    argmax_kernel<<<dim3(CMPL, Bx), 32>>>();

    /* 10) deterministic merge + cls copy -> xm */
    merge_kernel<<<dim3(LEFT, Bx), 256>>>();
    copy_cls_kernel<<<Bx, 256>>>();

    /* 11) LN2, 12) fc1+GELU (tf32 TC), 13) fc2+bias+residual (tf32 TC) -> out */
    ln_kernel<<<M2, 256>>>(pxm, n2w, n2b, pxn2);
    mma_gemm<3><<<dim3(FF/128, M2/128), 256>>>(pxn2, fc1w, fc1b, nullptr, ph1,
                                               M2, FF, Cx);
    mma_gemm<2><<<dim3(Cx/128, M2/128), 256>>>(ph1, fc2w, fc2b, pxm, out,
                                               M2, Cx, FF);
    (void)in_sizes; (void)n_in; (void)out_size;
}

// round 8
// speedup vs baseline: 1.5731x; 1.0388x over previous
#include <cuda_runtime.h>
#include <math.h>
#include <stdint.h>

#define Bx   128
#define Nx   197
#define Cx   768
#define Hx   12
#define Dx   64
#define NROWS 25216      /* Bx*Nx */
#define LEFT 138
#define CMPL 58
#define NM   139
#define M2   17792       /* Bx*NM */
#define FF   3072

/* ---------------- device scratch (no allocations allowed) ---------------- */
__device__ float g_xn [NROWS*Cx];
__device__ float g_qkv[NROWS*3*Cx];
__device__ float g_ao [NROWS*Cx];
__device__ float g_x1 [NROWS*Cx];
__device__ float g_clsh[Bx*Hx*196];
__device__ float g_cls[Bx*196];
__device__ int   g_idx[Bx*LEFT];
__device__ int   g_cmp[Bx*CMPL];
__device__ float g_NT[Bx*64*Cx];
__device__ float g_XO[Bx*144*Cx];
__device__ float g_nrm[Bx*LEFT];
__device__ float g_D[Bx*64*144];
__device__ int   g_node[Bx*CMPL];
__device__ float g_xm [M2*Cx];
__device__ float g_xn2[M2*Cx];
__device__ float g_h1 [M2*FF];

/* ---------------- cp.async helpers ---------------- */
__device__ __forceinline__ void cpasync16(uint32_t d, const void* s){
    asm volatile("cp.async.cg.shared.global [%0], [%1], 16;" :: "r"(d), "l"(s));
}
__device__ __forceinline__ void cp_commit(){ asm volatile("cp.async.commit_group;"); }
__device__ __forceinline__ void cp_wait0(){ asm volatile("cp.async.wait_group 0;"); }

/* ---------------- LayerNorm: one block per row, 256 thr, C=768 ---------------- */
__global__ __launch_bounds__(256) void ln_kernel(const float* __restrict__ x,
                                                 const float* __restrict__ w,
                                                 const float* __restrict__ bb,
                                                 float* __restrict__ y)
{
    int row = blockIdx.x;
    const float* xr = x + (size_t)row * Cx;
    float* yr = y + (size_t)row * Cx;
    int t = threadIdx.x;
    float v0 = xr[t], v1 = xr[t+256], v2 = xr[t+512];
    float s = v0+v1+v2;
    float q = v0*v0 + v1*v1 + v2*v2;
    __shared__ float sred[16];
    #pragma unroll
    for (int o=16;o;o>>=1){ s += __shfl_xor_sync(0xffffffffu,s,o); q += __shfl_xor_sync(0xffffffffu,q,o); }
    if ((t&31)==0){ sred[t>>5] = s; sred[8+(t>>5)] = q; }
    __syncthreads();
    s = 0.f; q = 0.f;
    #pragma unroll
    for (int i=0;i<8;i++){ s += sred[i]; q += sred[8+i]; }
    float mean = s * (1.0f/768.0f);
    float var  = q * (1.0f/768.0f) - mean*mean;
    float rstd = rsqrtf(var + 1e-5f);
    yr[t]     = (v0-mean)*rstd*w[t]     + bb[t];
    yr[t+256] = (v1-mean)*rstd*w[t+256] + bb[t+256];
    yr[t+512] = (v2-mean)*rstd*w[t+512] + bb[t+512];
}

/* ---------------- SGEMM v4: 128x128x8, 256 thr, 8x8/thread, fp32 ------------
   Software-pipelined: B via cp.async double-buffer, A via register prefetch
   (LDG tile k+1 before compute of tile k, transposed STS after), ONE sync
   per K-tile. Bit-exact vs v3 (same FFMA order). 2 CTAs/SM.
   EPI: 0 = none, 1 = +bias, 2 = +bias+residual, 3 = +bias+exact GELU        */
template<int EPI>
__global__ __launch_bounds__(256, 2) void sgemm(const float* __restrict__ A,
                                                const float* __restrict__ B,
                                                const float* __restrict__ bias,
                                                const float* __restrict__ res,
                                                float* __restrict__ C,
                                                int M, int N, int K)
{
    __shared__ float As[2][8][128];
    __shared__ float Bs[2][8][128];
    int tid = threadIdx.x;
    int bm = blockIdx.y << 7, bn = blockIdx.x << 7;
    const float* Ap = A + (size_t)(bm + (tid>>1))*K + ((tid&1)<<2);
    const float* Bp = B + (size_t)(tid>>5)*N + bn + ((tid&31)<<2);
    int tx = tid & 15, ty = tid >> 4;
    int arow = tid>>1, ac = (tid&1)<<2;

    uint32_t sB = (uint32_t)__cvta_generic_to_shared(&Bs[0][0][0]);
    uint32_t bDst0 = sB + (uint32_t)(((tid>>5)*128 + ((tid&31)<<2)) * 4);
    const uint32_t B_BUF = 8*128*4;

    float acc[8][8];
    #pragma unroll
    for (int i=0;i<8;i++)
        #pragma unroll
        for (int j=0;j<8;j++) acc[i][j] = 0.f;

    /* prologue: stage tile 0 */
    cpasync16(bDst0, Bp);
    cp_commit();
    float4 av = *(const float4*)Ap;
    As[0][ac+0][arow]=av.x; As[0][ac+1][arow]=av.y;
    As[0][ac+2][arow]=av.z; As[0][ac+3][arow]=av.w;

    int KT = K >> 3;
    for (int kt = 0; kt < KT; kt++){
        int cur = kt & 1;
        cp_wait0();
        __syncthreads();          /* B(kt) visible; A(kt) STS visible;
                                     buffer nxt free for reuse            */
        if (kt < KT-1){
            int nxt = cur ^ 1;
            cpasync16(bDst0 + (uint32_t)nxt * B_BUF, Bp + (size_t)(kt+1)*8*N);
            cp_commit();
            av = *(const float4*)(Ap + ((kt+1) << 3));   /* latency hidden */
        }
        #pragma unroll
        for (int kk=0;kk<8;kk++){
            float a[8], b[8];
            *(float4*)(a)   = *(const float4*)&As[cur][kk][ty<<3];
            *(float4*)(a+4) = *(const float4*)&As[cur][kk][(ty<<3)+4];
            *(float4*)(b)   = *(const float4*)&Bs[cur][kk][tx<<2];
            *(float4*)(b+4) = *(const float4*)&Bs[cur][kk][64+(tx<<2)];
            #pragma unroll
            for (int i=0;i<8;i++)
                #pragma unroll
                for (int j=0;j<8;j++)
                    acc[i][j] = fmaf(a[i], b[j], acc[i][j]);
        }
        if (kt < KT-1){
            int nxt = cur ^ 1;
            As[nxt][ac+0][arow]=av.x; As[nxt][ac+1][arow]=av.y;
            As[nxt][ac+2][arow]=av.z; As[nxt][ac+3][arow]=av.w;
        }
    }
    /* epilogue: rows bm+ty*8+i, col groups {bn+tx*4, bn+64+tx*4} */
    #pragma unroll
    for (int i=0;i<8;i++){
        int row = bm + (ty<<3) + i;
        #pragma unroll
        for (int half=0;half<2;half++){
            int col = bn + (half<<6) + (tx<<2);
            size_t off = (size_t)row*N + col;
            float4 v;
            v.x = acc[i][half*4+0];
            v.y = acc[i][half*4+1];
            v.z = acc[i][half*4+2];
            v.w = acc[i][half*4+3];
            if (EPI >= 1){
                float4 bb4 = *(const float4*)&bias[col];
                v.x += bb4.x; v.y += bb4.y; v.z += bb4.z; v.w += bb4.w;
            }
            if (EPI == 2){
                float4 r4 = *(const float4*)&res[off];
                v.x += r4.x; v.y += r4.y; v.z += r4.z; v.w += r4.w;
            }
            if (EPI == 3){
                v.x = 0.5f*v.x*(1.0f + erff(v.x*0.70710678118654752f));
                v.y = 0.5f*v.y*(1.0f + erff(v.y*0.70710678118654752f));
                v.z = 0.5f*v.z*(1.0f + erff(v.z*0.70710678118654752f));
                v.w = 0.5f*v.w*(1.0f + erff(v.w*0.70710678118654752f));
            }
            *(float4*)(C + off) = v;
        }
    }
}

/* ---------------- TF32 tensor-core GEMM v2 (mma.sync m16n8k8) --------------
   128x128x16 tile, 256 thr (8 warps, 2x4 warp grid, 64x32 warp tiles).
   cp.async staging, raw-fp32-bit tf32 feed, 2 CTAs/SM.
   EPI: 2 = +bias+residual, 3 = +bias+exact GELU. M%128==0, N%128==0, K%16==0 */
template<int EPI>
__global__ __launch_bounds__(256, 2) void mma_gemm(const float* __restrict__ A,
                                                   const float* __restrict__ B,
                                                   const float* __restrict__ bias,
                                                   const float* __restrict__ res,
                                                   float* __restrict__ C,
                                                   int M, int N, int K)
{
    __shared__ float As[2][128][20];   /* padded: frag LDS conflict-free */
    __shared__ float Bs[2][16][136];

    int tid = threadIdx.x;
    int bm = blockIdx.y << 7, bn = blockIdx.x << 7;
    int lane = tid & 31, warp = tid >> 5;
    int wm = (warp >> 2) << 6;         /* 0 or 64  */
    int wn = (warp & 3) << 5;          /* 0,32,64,96 */
    int gq = lane >> 2, gr = lane & 3;

    int ar = tid >> 1, ac = (tid & 1) << 3;
    int br = tid >> 4, bc = (tid & 15) << 3;
    const float* Ag = A + (size_t)(bm + ar)*K + ac;
    const float* Bg = B + (size_t)br*N + bn + bc;

    uint32_t sA = (uint32_t)__cvta_generic_to_shared(&As[0][0][0]);
    uint32_t sB = (uint32_t)__cvta_generic_to_shared(&Bs[0][0][0]);
    uint32_t aDst0 = sA + (uint32_t)(ar*80 + ac*4);
    uint32_t bDst0 = sB + (uint32_t)(br*544 + bc*4);
    const uint32_t A_BUF = 128*20*4, B_BUF = 16*136*4;

    float acc[4][4][4];
    #pragma unroll
    for (int mi=0;mi<4;mi++)
        #pragma unroll
        for (int ni=0;ni<4;ni++)
            #pragma unroll
            for (int r=0;r<4;r++) acc[mi][ni][r] = 0.f;

    /* prologue: stage tile 0 */
    cpasync16(aDst0,      Ag);
    cpasync16(aDst0 + 16, Ag + 4);
    cpasync16(bDst0,      Bg);
    cpasync16(bDst0 + 16, Bg + 4);
    cp_commit();

    int KT = K >> 4;
    for (int kt = 0; kt < KT; kt++){
        int cur = kt & 1;
        cp_wait0();
        __syncthreads();
        if (kt < KT-1){
            int nxt = cur ^ 1;
            const float* Ag2 = Ag + ((kt+1) << 4);
            const float* Bg2 = Bg + (size_t)((kt+1) << 4) * N;
            uint32_t ad = aDst0 + (uint32_t)nxt * A_BUF;
            uint32_t bd = bDst0 + (uint32_t)nxt * B_BUF;
            cpasync16(ad,      Ag2);
            cpasync16(ad + 16, Ag2 + 4);
            cpasync16(bd,      Bg2);
            cpasync16(bd + 16, Bg2 + 4);
            cp_commit();
        }
        #pragma unroll
        for (int ks = 0; ks < 16; ks += 8){
            uint32_t Af[4][4], Bf[4][2];
            #pragma unroll
            for (int mi=0;mi<4;mi++){
                int m0 = wm + (mi<<4) + gq;
                Af[mi][0] = __float_as_uint(As[cur][m0  ][ks+gr]);
                Af[mi][1] = __float_as_uint(As[cur][m0+8][ks+gr]);
                Af[mi][2] = __float_as_uint(As[cur][m0  ][ks+4+gr]);
                Af[mi][3] = __float_as_uint(As[cur][m0+8][ks+4+gr]);
            }
            #pragma unroll
            for (int ni=0;ni<4;ni++){
                int n0 = wn + (ni<<3) + gq;
                Bf[ni][0] = __float_as_uint(Bs[cur][ks+gr  ][n0]);
                Bf[ni][1] = __float_as_uint(Bs[cur][ks+4+gr][n0]);
            }
            #pragma unroll
            for (int mi=0;mi<4;mi++)
                #pragma unroll
                for (int ni=0;ni<4;ni++){
                    asm volatile(
                        "mma.sync.aligned.m16n8k8.row.col.f32.tf32.tf32.f32 "
                        "{%0,%1,%2,%3}, {%4,%5,%6,%7}, {%8,%9}, {%0,%1,%2,%3};"
                        : "+f"(acc[mi][ni][0]), "+f"(acc[mi][ni][1]),
                          "+f"(acc[mi][ni][2]), "+f"(acc[mi][ni][3])
                        : "r"(Af[mi][0]), "r"(Af[mi][1]), "r"(Af[mi][2]), "r"(Af[mi][3]),
                          "r"(Bf[ni][0]), "r"(Bf[ni][1]));
                }
        }
    }

    /* epilogue */
    #pragma unroll
    for (int mi=0;mi<4;mi++){
        int row = bm + wm + (mi<<4) + gq;
        #pragma unroll
        for (int ni=0;ni<4;ni++){
            int col = bn + wn + (ni<<3) + (gr<<1);
            float b0 = bias[col], b1 = bias[col+1];
            size_t o0 = (size_t)row*N + col;
            size_t o1 = (size_t)(row+8)*N + col;
            float v00 = acc[mi][ni][0] + b0;
            float v01 = acc[mi][ni][1] + b1;
            float v10 = acc[mi][ni][2] + b0;
            float v11 = acc[mi][ni][3] + b1;
            if (EPI == 2){
                v00 += res[o0];   v01 += res[o0+1];
                v10 += res[o1];   v11 += res[o1+1];
            }
            if (EPI == 3){
                v00 = 0.5f*v00*(1.0f + erff(v00*0.70710678118654752f));
                v01 = 0.5f*v01*(1.0f + erff(v01*0.70710678118654752f));
                v10 = 0.5f*v10*(1.0f + erff(v10*0.70710678118654752f));
                v11 = 0.5f*v11*(1.0f + erff(v11*0.70710678118654752f));
            }
            float2 w0; w0.x = v00; w0.y = v01;
            float2 w1; w1.x = v10; w1.y = v11;
            *(float2*)(C + o0) = w0;
            *(float2*)(C + o1) = w1;
        }
    }
}

/* ---------------- Attention: one block per (head, batch) ----------------
   Q,K,V (197x64 fp32 each, padded to 65 cols) + per-warp prob rows in smem */
#define QKV_PAD 65
#define QKV_SZ  (Nx*QKV_PAD)            /* 12805 */
#define SMEM_ATTN_FLOATS (3*QKV_SZ + 8*200)
__global__ __launch_bounds__(256) void attn_kernel(const float* __restrict__ qkv,
                                                   float* __restrict__ out,
                                                   float* __restrict__ clsh)
{
    extern __shared__ float sm[];
    float* Qs = sm;
    float* Ks = sm + QKV_SZ;
    float* Vs = sm + 2*QKV_SZ;
    float* Pb = sm + 3*QKV_SZ;
    int h = blockIdx.x, b = blockIdx.y;
    int tid = threadIdx.x, warp = tid>>5, lane = tid&31;

    const float* base = qkv + (size_t)b*Nx*2304 + h*64;
    for (int i = tid; i < Nx*64; i += 256){
        int n = i>>6, c = i&63;
        size_t s = (size_t)n*2304 + c;
        Qs[n*QKV_PAD+c] = base[s];
        Ks[n*QKV_PAD+c] = base[s+768];
        Vs[n*QKV_PAD+c] = base[s+1536];
    }
    __syncthreads();

    float* pb = Pb + warp*200;
    for (int i = warp; i < Nx; i += 8){
        const float* qr = Qs + i*QKV_PAD;
        float sc[7];
        int joff[7];
        #pragma unroll
        for (int t=0;t<7;t++){ sc[t]=0.f; int j=lane+32*t; joff[t] = (j<Nx ? j : 0)*QKV_PAD; }
        #pragma unroll 4
        for (int c=0;c<64;c++){
            float qc = qr[c];
            #pragma unroll
            for (int t=0;t<7;t++) sc[t] = fmaf(qc, Ks[joff[t]+c], sc[t]);
        }
        float mx = -3.0e38f;
        #pragma unroll
        for (int t=0;t<7;t++){
            int j=lane+32*t;
            sc[t] = (j<Nx) ? sc[t]*0.125f : -3.0e38f;
            mx = fmaxf(mx, sc[t]);
        }
        #pragma unroll
        for (int o=16;o;o>>=1) mx = fmaxf(mx, __shfl_xor_sync(0xffffffffu, mx, o));
        float sum = 0.f;
        #pragma unroll
        for (int t=0;t<7;t++){
            int j=lane+32*t;
            float e = (j<Nx) ? expf(sc[t]-mx) : 0.f;
            sc[t]=e; sum+=e;
        }
        #pragma unroll
        for (int o=16;o;o>>=1) sum += __shfl_xor_sync(0xffffffffu, sum, o);
        float inv = 1.0f/sum;
        #pragma unroll
        for (int t=0;t<7;t++){
            int j=lane+32*t;
            if (j<Nx) pb[j] = sc[t]*inv;
        }
        __syncwarp();
        if (i == 0){
            #pragma unroll
            for (int t=0;t<7;t++){
                int j=lane+32*t;
                if (j>=1 && j<Nx) clsh[((size_t)b*Hx + h)*196 + (j-1)] = sc[t]*inv;
            }
        }
        float o0=0.f, o1=0.f;
        for (int j=0;j<Nx;j++){
            float p = pb[j];
            o0 = fmaf(p, Vs[j*QKV_PAD+lane], o0);
            o1 = fmaf(p, Vs[j*QKV_PAD+lane+32], o1);
        }
        size_t oo = (size_t)(b*Nx + i)*Cx + h*64;
        out[oo + lane]      = o0;
        out[oo + lane + 32] = o1;
        __syncwarp();
    }
}

/* ---------------- cls_attn = mean over heads (deterministic) ---------------- */
__global__ void cls_mean_kernel()
{
    int b = blockIdx.x, j = threadIdx.x;
    if (j < 196){
        float s = 0.f;
        #pragma unroll
        for (int h=0; h<Hx; h++) s += g_clsh[((size_t)b*Hx + h)*196 + j];
        g_cls[b*196 + j] = s * (1.0f/12.0f);
    }
}

/* ---------------- top-k (138 of 196) via bitonic sort + complement --------- */
__global__ __launch_bounds__(256) void topk_kernel()
{
    __shared__ float v[256];
    __shared__ int   id[256];
    __shared__ unsigned char sel[196];
    int b = blockIdx.x, t = threadIdx.x;
    v[t]  = (t < 196) ? g_cls[b*196 + t] : -3.0e38f;
    id[t] = t;
    __syncthreads();
    for (int k=2;k<=256;k<<=1){
        for (int j=k>>1;j>0;j>>=1){
            int ixj = t ^ j;
            if (ixj > t){
                float va=v[t], vb=v[ixj];
                int   ia=id[t], ib=id[ixj];
                bool aWorse = (va < vb) || (va == vb && ia > ib);
                bool dirDesc = ((t & k) == 0);
                bool doswap = dirDesc ? aWorse : !aWorse;
                if (doswap){ v[t]=vb; v[ixj]=va; id[t]=ib; id[ixj]=ia; }
            }
            __syncthreads();
        }
    }
    if (t < LEFT) g_idx[b*LEFT + t] = id[t];
    if (t < 196) sel[t] = 0;
    __syncthreads();
    if (t < LEFT) sel[id[t]] = 1;
    __syncthreads();
    if (t == 0){
        int c = 0;
        for (int j=0;j<196;j++) if (!sel[j]) g_cmp[b*CMPL + (c++)] = j;
    }
}

/* ---------------- gathers (padded for the distance GEMM) ---------------- */
__global__ __launch_bounds__(256) void gather_xo_kernel()
{
    int l = blockIdx.x, b = blockIdx.y, t = threadIdx.x;
    float* dst = g_XO + ((size_t)b*144 + l)*Cx;
    float ss = 0.f;
    if (l < LEFT){
        int j = g_idx[b*LEFT + l];
        const float* src = g_x1 + ((size_t)(b*Nx) + 1 + j)*Cx;
        #pragma unroll
        for (int r=0;r<3;r++){
            float vv = src[t + r*256];
            dst[t + r*256] = vv;
            ss += vv*vv;
        }
    } else {
        #pragma unroll
        for (int r=0;r<3;r++) dst[t + r*256] = 0.f;
    }
    __shared__ float sr[8];
    #pragma unroll
    for (int o=16;o;o>>=1) ss += __shfl_xor_sync(0xffffffffu, ss, o);
    if ((t&31)==0) sr[t>>5] = ss;
    __syncthreads();
    if (t == 0 && l < LEFT){
        float tot = 0.f;
        #pragma unroll
        for (int i=0;i<8;i++) tot += sr[i];
        g_nrm[b*LEFT + l] = sqrtf(tot);
    }
}

__global__ __launch_bounds__(256) void gather_nt_kernel()
{
    int m = blockIdx.x, b = blockIdx.y, t = threadIdx.x;
    float* dst = g_NT + ((size_t)b*64 + m)*Cx;
    if (m < CMPL){
        int j = g_cmp[b*CMPL + m];
        const float* src = g_x1 + ((size_t)(b*Nx) + 1 + j)*Cx;
        #pragma unroll
        for (int r=0;r<3;r++) dst[t + r*256] = src[t + r*256];
    } else {
        #pragma unroll
        for (int r=0;r<3;r++) dst[t + r*256] = 0.f;
    }
}

/* ---------------- distance GEMM: per batch, D[64pad,144pad] = NT @ XO^T ---- */
__global__ __launch_bounds__(256) void dist_kernel()
{
    __shared__ float NTs[64*33];
    __shared__ float XOs[144*33];
    int b = blockIdx.x, tid = threadIdx.x;
    int tx = tid & 15, ty = tid >> 4;
    const float* NTb = g_NT + (size_t)b*64*Cx;
    const float* XOb = g_XO + (size_t)b*144*Cx;
    float acc[4][9];
    #pragma unroll
    for (int i=0;i<4;i++)
        #pragma unroll
        for (int j=0;j<9;j++) acc[i][j]=0.f;

    for (int k0=0;k0<Cx;k0+=32){
        for (int i=tid;i<64*32;i+=256){ int m=i>>5, kk=i&31; NTs[m*33+kk]=NTb[(size_t)m*Cx+k0+kk]; }
        for (int i=tid;i<144*32;i+=256){ int l=i>>5, kk=i&31; XOs[l*33+kk]=XOb[(size_t)l*Cx+k0+kk]; }
        __syncthreads();
        #pragma unroll 8
        for (int kk=0;kk<32;kk++){
            float a[4], bb2[9];
            #pragma unroll
            for (int ii=0;ii<4;ii++) a[ii]  = NTs[(ty*4+ii)*33 + kk];
            #pragma unroll
            for (int jj=0;jj<9;jj++) bb2[jj]= XOs[(tx*9+jj)*33 + kk];
            #pragma unroll
            for (int ii=0;ii<4;ii++)
                #pragma unroll
                for (int jj=0;jj<9;jj++)
                    acc[ii][jj] = fmaf(a[ii], bb2[jj], acc[ii][jj]);
        }
        __syncthreads();
    }
    #pragma unroll
    for (int ii=0;ii<4;ii++)
        #pragma unroll
        for (int jj=0;jj<9;jj++)
            g_D[(size_t)b*9216 + (ty*4+ii)*144 + (tx*9+jj)] = acc[ii][jj];
}

/* ---------------- argmax over topk (first-max tie rule, matches jnp) ------- */
__global__ void argmax_kernel()
{
    int m = blockIdx.x, b = blockIdx.y, lane = threadIdx.x;
    const float* Dr = g_D + (size_t)b*9216 + m*144;
    float best = -3.0e38f; int bi = 1<<30;
    for (int l=lane; l<LEFT; l+=32){
        float v = Dr[l] / g_nrm[b*LEFT + l];
        if (v > best || (v == best && l < bi)){ best = v; bi = l; }
    }
    #pragma unroll
    for (int o=16;o;o>>=1){
        float v2 = __shfl_xor_sync(0xffffffffu, best, o);
        int   i2 = __shfl_xor_sync(0xffffffffu, bi,   o);
        if (v2 > best || (v2 == best && i2 < bi)){ best = v2; bi = i2; }
    }
    if (lane == 0) g_node[b*CMPL + m] = bi;
}

/* ---------------- deterministic merge (no atomics): one block per (l,b) ---- */
__global__ __launch_bounds__(256) void merge_kernel()
{
    int l = blockIdx.x, b = blockIdx.y, t = threadIdx.x;
    int jt = g_idx[b*LEFT + l];
    float w = g_cls[b*196 + jt];
    const float* src = g_x1 + ((size_t)(b*Nx) + 1 + jt)*Cx;
    float a0 = src[t]*w, a1 = src[t+256]*w, a2 = src[t+512]*w;
    float tka = w;
    for (int m=0;m<CMPL;m++){
        if (g_node[b*CMPL + m] == l){
            int jm = g_cmp[b*CMPL + m];
            float wm = g_cls[b*196 + jm];
            const float* s2 = g_x1 + ((size_t)(b*Nx) + 1 + jm)*Cx;
            a0 += s2[t]*wm; a1 += s2[t+256]*wm; a2 += s2[t+512]*wm;
            tka += wm;
        }
    }
    float* dst = g_xm + ((size_t)(b*NM) + 1 + l)*Cx;
    dst[t]     = a0 / tka;
    dst[t+256] = a1 / tka;
    dst[t+512] = a2 / tka;
}

__global__ void copy_cls_kernel()
{
    int b = blockIdx.x, t = threadIdx.x;
    const float* s = g_x1 + (size_t)b*Nx*Cx;
    float* d = g_xm + (size_t)b*NM*Cx;
    #pragma unroll
    for (int r=0;r<3;r++) d[t + r*256] = s[t + r*256];
}

/* ---------------- host launcher ---------------- */
extern "C" void kernel_launch(void* const* d_in, const int* in_sizes, int n_in,
                              void* d_out, int out_size)
{
    const float* x     = (const float*)d_in[0];
    const float* n1w   = (const float*)d_in[1];
    const float* n1b   = (const float*)d_in[2];
    const float* qkvw  = (const float*)d_in[3];
    const float* projw = (const float*)d_in[4];
    const float* projb = (const float*)d_in[5];
    const float* n2w   = (const float*)d_in[6];
    const float* n2b   = (const float*)d_in[7];
    const float* fc1w  = (const float*)d_in[8];
    const float* fc1b  = (const float*)d_in[9];
    const float* fc2w  = (const float*)d_in[10];
    const float* fc2b  = (const float*)d_in[11];
    float* out = (float*)d_out;

    void *p;
    cudaGetSymbolAddress(&p, g_xn);   float* pxn  = (float*)p;
    cudaGetSymbolAddress(&p, g_qkv);  float* pqkv = (float*)p;
    cudaGetSymbolAddress(&p, g_ao);   float* pao  = (float*)p;
    cudaGetSymbolAddress(&p, g_x1);   float* px1  = (float*)p;
    cudaGetSymbolAddress(&p, g_clsh); float* pclsh= (float*)p;
    cudaGetSymbolAddress(&p, g_xm);   float* pxm  = (float*)p;
    cudaGetSymbolAddress(&p, g_xn2);  float* pxn2 = (float*)p;
    cudaGetSymbolAddress(&p, g_h1);   float* ph1  = (float*)p;

    /* 1) LN1 */
    ln_kernel<<<NROWS, 256>>>(x, n1w, n1b, pxn);

    /* 2) QKV GEMM: [25216,768] x [768,2304]  (fp32 — feeds top-k selection) */
    sgemm<0><<<dim3(2304/128, NROWS/128), 256>>>(pxn, qkvw, nullptr, nullptr, pqkv,
                                                 NROWS, 2304, Cx);

    /* 3) attention per (head, batch) */
    cudaFuncSetAttribute(attn_kernel, cudaFuncAttributeMaxDynamicSharedMemorySize,
                         SMEM_ATTN_FLOATS*4);
    attn_kernel<<<dim3(Hx, Bx), 256, SMEM_ATTN_FLOATS*4>>>(pqkv, pao, pclsh);

    /* 4) proj GEMM + bias + residual(x) -> x1 (fp32 — feeds argmax selection) */
    sgemm<2><<<dim3(Cx/128, NROWS/128), 256>>>(pao, projw, projb, x, px1,
                                               NROWS, Cx, Cx);

    /* 5) cls attention mean over heads, 6) top-k + complement */
    cls_mean_kernel<<<Bx, 256>>>();
    topk_kernel<<<Bx, 256>>>();

    /* 7) gathers + norms, 8) cosine distance GEMM, 9) argmax */
    gather_xo_kernel<<<dim3(144, Bx), 256>>>();
    gather_nt_kernel<<<dim3(64, Bx), 256>>>();
    dist_kernel<<<Bx, 256>>>();
    argmax_kernel<<<dim3(CMPL, Bx), 32>>>();

    /* 10) deterministic merge + cls copy -> xm */
    merge_kernel<<<dim3(LEFT, Bx), 256>>>();
    copy_cls_kernel<<<Bx, 256>>>();

    /* 11) LN2, 12) fc1+GELU (tf32 TC), 13) fc2+bias+residual (tf32 TC) -> out */
    ln_kernel<<<M2, 256>>>(pxm, n2w, n2b, pxn2);
    mma_gemm<3><<<dim3(FF/128, M2/128), 256>>>(pxn2, fc1w, fc1b, nullptr, ph1,
                                               M2, FF, Cx);
    mma_gemm<2><<<dim3(Cx/128, M2/128), 256>>>(ph1, fc2w, fc2b, pxm, out,
                                               M2, Cx, FF);
    (void)in_sizes; (void)n_in; (void)out_size;
}

// round 11
// speedup vs baseline: 1.8464x; 1.1737x over previous
#include <cuda_runtime.h>
#include <math.h>
#include <stdint.h>

#define Bx   128
#define Nx   197
#define Cx   768
#define Hx   12
#define Dx   64
#define NROWS 25216      /* Bx*Nx */
#define LEFT 138
#define CMPL 58
#define NM   139
#define M2   17792       /* Bx*NM */
#define FF   3072

/* ---------------- device scratch (no allocations allowed) ---------------- */
__device__ float g_xn [NROWS*Cx];
__device__ float g_qkv[NROWS*3*Cx];
__device__ float g_ao [NROWS*Cx];
__device__ float g_x1 [NROWS*Cx];
__device__ float g_clsh[Bx*Hx*196];
__device__ float g_cls[Bx*196];
__device__ int   g_idx[Bx*LEFT];
__device__ int   g_cmp[Bx*CMPL];
__device__ float g_NT[Bx*64*Cx];
__device__ float g_XO[Bx*144*Cx];
__device__ float g_nrm[Bx*LEFT];
__device__ float g_D[Bx*64*144];
__device__ int   g_node[Bx*CMPL];
__device__ float g_xm [M2*Cx];
__device__ float g_xn2[M2*Cx];
__device__ float g_h1 [M2*FF];

/* ---------------- cp.async helpers ---------------- */
__device__ __forceinline__ void cpasync16(uint32_t d, const void* s){
    asm volatile("cp.async.cg.shared.global [%0], [%1], 16;" :: "r"(d), "l"(s));
}
__device__ __forceinline__ void cp_commit(){ asm volatile("cp.async.commit_group;"); }
__device__ __forceinline__ void cp_wait0(){ asm volatile("cp.async.wait_group 0;"); }

/* ---------------- LayerNorm ---------------- */
__global__ __launch_bounds__(256) void ln_kernel(const float* __restrict__ x,
                                                 const float* __restrict__ w,
                                                 const float* __restrict__ bb,
                                                 float* __restrict__ y)
{
    int row = blockIdx.x;
    const float* xr = x + (size_t)row * Cx;
    float* yr = y + (size_t)row * Cx;
    int t = threadIdx.x;
    float v0 = xr[t], v1 = xr[t+256], v2 = xr[t+512];
    float s = v0+v1+v2;
    float q = v0*v0 + v1*v1 + v2*v2;
    __shared__ float sred[16];
    #pragma unroll
    for (int o=16;o;o>>=1){ s += __shfl_xor_sync(0xffffffffu,s,o); q += __shfl_xor_sync(0xffffffffu,q,o); }
    if ((t&31)==0){ sred[t>>5] = s; sred[8+(t>>5)] = q; }
    __syncthreads();
    s = 0.f; q = 0.f;
    #pragma unroll
    for (int i=0;i<8;i++){ s += sred[i]; q += sred[8+i]; }
    float mean = s * (1.0f/768.0f);
    float var  = q * (1.0f/768.0f) - mean*mean;
    float rstd = rsqrtf(var + 1e-5f);
    yr[t]     = (v0-mean)*rstd*w[t]     + bb[t];
    yr[t+256] = (v1-mean)*rstd*w[t+256] + bb[t+256];
    yr[t+512] = (v2-mean)*rstd*w[t+512] + bb[t+512];
}

/* ---------------- SGEMM v4 (proven R8): 128x128x8, pipelined, bit-exact --- */
template<int EPI>
__global__ __launch_bounds__(256, 2) void sgemm(const float* __restrict__ A,
                                                const float* __restrict__ B,
                                                const float* __restrict__ bias,
                                                const float* __restrict__ res,
                                                float* __restrict__ C,
                                                int M, int N, int K)
{
    __shared__ float As[2][8][128];
    __shared__ float Bs[2][8][128];
    int tid = threadIdx.x;
    int bm = blockIdx.y << 7, bn = blockIdx.x << 7;
    const float* Ap = A + (size_t)(bm + (tid>>1))*K + ((tid&1)<<2);
    const float* Bp = B + (size_t)(tid>>5)*N + bn + ((tid&31)<<2);
    int tx = tid & 15, ty = tid >> 4;
    int arow = tid>>1, ac = (tid&1)<<2;

    uint32_t sB = (uint32_t)__cvta_generic_to_shared(&Bs[0][0][0]);
    uint32_t bDst0 = sB + (uint32_t)(((tid>>5)*128 + ((tid&31)<<2)) * 4);
    const uint32_t B_BUF = 8*128*4;

    float acc[8][8];
    #pragma unroll
    for (int i=0;i<8;i++)
        #pragma unroll
        for (int j=0;j<8;j++) acc[i][j] = 0.f;

    cpasync16(bDst0, Bp);
    cp_commit();
    float4 av = *(const float4*)Ap;
    As[0][ac+0][arow]=av.x; As[0][ac+1][arow]=av.y;
    As[0][ac+2][arow]=av.z; As[0][ac+3][arow]=av.w;

    int KT = K >> 3;
    for (int kt = 0; kt < KT; kt++){
        int cur = kt & 1;
        cp_wait0();
        __syncthreads();
        if (kt < KT-1){
            int nxt = cur ^ 1;
            cpasync16(bDst0 + (uint32_t)nxt * B_BUF, Bp + (size_t)(kt+1)*8*N);
            cp_commit();
            av = *(const float4*)(Ap + ((kt+1) << 3));
        }
        #pragma unroll
        for (int kk=0;kk<8;kk++){
            float a[8], b[8];
            *(float4*)(a)   = *(const float4*)&As[cur][kk][ty<<3];
            *(float4*)(a+4) = *(const float4*)&As[cur][kk][(ty<<3)+4];
            *(float4*)(b)   = *(const float4*)&Bs[cur][kk][tx<<2];
            *(float4*)(b+4) = *(const float4*)&Bs[cur][kk][64+(tx<<2)];
            #pragma unroll
            for (int i=0;i<8;i++)
                #pragma unroll
                for (int j=0;j<8;j++)
                    acc[i][j] = fmaf(a[i], b[j], acc[i][j]);
        }
        if (kt < KT-1){
            int nxt = cur ^ 1;
            As[nxt][ac+0][arow]=av.x; As[nxt][ac+1][arow]=av.y;
            As[nxt][ac+2][arow]=av.z; As[nxt][ac+3][arow]=av.w;
        }
    }
    #pragma unroll
    for (int i=0;i<8;i++){
        int row = bm + (ty<<3) + i;
        #pragma unroll
        for (int half=0;half<2;half++){
            int col = bn + (half<<6) + (tx<<2);
            size_t off = (size_t)row*N + col;
            float4 v;
            v.x = acc[i][half*4+0];
            v.y = acc[i][half*4+1];
            v.z = acc[i][half*4+2];
            v.w = acc[i][half*4+3];
            if (EPI >= 1){
                float4 bb4 = *(const float4*)&bias[col];
                v.x += bb4.x; v.y += bb4.y; v.z += bb4.z; v.w += bb4.w;
            }
            if (EPI == 2){
                float4 r4 = *(const float4*)&res[off];
                v.x += r4.x; v.y += r4.y; v.z += r4.z; v.w += r4.w;
            }
            if (EPI == 3){
                v.x = 0.5f*v.x*(1.0f + erff(v.x*0.70710678118654752f));
                v.y = 0.5f*v.y*(1.0f + erff(v.y*0.70710678118654752f));
                v.z = 0.5f*v.z*(1.0f + erff(v.z*0.70710678118654752f));
                v.w = 0.5f*v.w*(1.0f + erff(v.w*0.70710678118654752f));
            }
            *(float4*)(C + off) = v;
        }
    }
}

/* ---------------- TF32 tensor-core GEMM (mma.sync m16n8k8, proven R8) ------
   128x128x16 tile, 256 thr, cp.async staging, raw-fp32-bit tf32 feed,
   2 CTAs/SM. EPI: 2 = +bias+residual, 3 = +bias+exact GELU.                */
template<int EPI>
__global__ __launch_bounds__(256, 2) void mma_gemm(const float* __restrict__ A,
                                                   const float* __restrict__ B,
                                                   const float* __restrict__ bias,
                                                   const float* __restrict__ res,
                                                   float* __restrict__ C,
                                                   int M, int N, int K)
{
    __shared__ float As[2][128][20];
    __shared__ float Bs[2][16][136];

    int tid = threadIdx.x;
    int bm = blockIdx.y << 7, bn = blockIdx.x << 7;
    int lane = tid & 31, warp = tid >> 5;
    int wm = (warp >> 2) << 6;
    int wn = (warp & 3) << 5;
    int gq = lane >> 2, gr = lane & 3;

    int ar = tid >> 1, ac = (tid & 1) << 3;
    int br = tid >> 4, bc = (tid & 15) << 3;
    const float* Ag = A + (size_t)(bm + ar)*K + ac;
    const float* Bg = B + (size_t)br*N + bn + bc;

    uint32_t sA = (uint32_t)__cvta_generic_to_shared(&As[0][0][0]);
    uint32_t sB = (uint32_t)__cvta_generic_to_shared(&Bs[0][0][0]);
    uint32_t aDst0 = sA + (uint32_t)(ar*80 + ac*4);
    uint32_t bDst0 = sB + (uint32_t)(br*544 + bc*4);
    const uint32_t A_BUF = 128*20*4, B_BUF = 16*136*4;

    float acc[4][4][4];
    #pragma unroll
    for (int mi=0;mi<4;mi++)
        #pragma unroll
        for (int ni=0;ni<4;ni++)
            #pragma unroll
            for (int r=0;r<4;r++) acc[mi][ni][r] = 0.f;

    cpasync16(aDst0,      Ag);
    cpasync16(aDst0 + 16, Ag + 4);
    cpasync16(bDst0,      Bg);
    cpasync16(bDst0 + 16, Bg + 4);
    cp_commit();

    int KT = K >> 4;
    for (int kt = 0; kt < KT; kt++){
        int cur = kt & 1;
        cp_wait0();
        __syncthreads();
        if (kt < KT-1){
            int nxt = cur ^ 1;
            const float* Ag2 = Ag + ((kt+1) << 4);
            const float* Bg2 = Bg + (size_t)((kt+1) << 4) * N;
            uint32_t ad = aDst0 + (uint32_t)nxt * A_BUF;
            uint32_t bd = bDst0 + (uint32_t)nxt * B_BUF;
            cpasync16(ad,      Ag2);
            cpasync16(ad + 16, Ag2 + 4);
            cpasync16(bd,      Bg2);
            cpasync16(bd + 16, Bg2 + 4);
            cp_commit();
        }
        #pragma unroll
        for (int ks = 0; ks < 16; ks += 8){
            uint32_t Af[4][4], Bf[4][2];
            #pragma unroll
            for (int mi=0;mi<4;mi++){
                int m0 = wm + (mi<<4) + gq;
                Af[mi][0] = __float_as_uint(As[cur][m0  ][ks+gr]);
                Af[mi][1] = __float_as_uint(As[cur][m0+8][ks+gr]);
                Af[mi][2] = __float_as_uint(As[cur][m0  ][ks+4+gr]);
                Af[mi][3] = __float_as_uint(As[cur][m0+8][ks+4+gr]);
            }
            #pragma unroll
            for (int ni=0;ni<4;ni++){
                int n0 = wn + (ni<<3) + gq;
                Bf[ni][0] = __float_as_uint(Bs[cur][ks+gr  ][n0]);
                Bf[ni][1] = __float_as_uint(Bs[cur][ks+4+gr][n0]);
            }
            #pragma unroll
            for (int mi=0;mi<4;mi++)
                #pragma unroll
                for (int ni=0;ni<4;ni++){
                    asm volatile(
                        "mma.sync.aligned.m16n8k8.row.col.f32.tf32.tf32.f32 "
                        "{%0,%1,%2,%3}, {%4,%5,%6,%7}, {%8,%9}, {%0,%1,%2,%3};"
                        : "+f"(acc[mi][ni][0]), "+f"(acc[mi][ni][1]),
                          "+f"(acc[mi][ni][2]), "+f"(acc[mi][ni][3])
                        : "r"(Af[mi][0]), "r"(Af[mi][1]), "r"(Af[mi][2]), "r"(Af[mi][3]),
                          "r"(Bf[ni][0]), "r"(Bf[ni][1]));
                }
        }
    }

    #pragma unroll
    for (int mi=0;mi<4;mi++){
        int row = bm + wm + (mi<<4) + gq;
        #pragma unroll
        for (int ni=0;ni<4;ni++){
            int col = bn + wn + (ni<<3) + (gr<<1);
            float b0 = bias[col], b1 = bias[col+1];
            size_t o0 = (size_t)row*N + col;
            size_t o1 = (size_t)(row+8)*N + col;
            float v00 = acc[mi][ni][0] + b0;
            float v01 = acc[mi][ni][1] + b1;
            float v10 = acc[mi][ni][2] + b0;
            float v11 = acc[mi][ni][3] + b1;
            if (EPI == 2){
                v00 += res[o0];   v01 += res[o0+1];
                v10 += res[o1];   v11 += res[o1+1];
            }
            if (EPI == 3){
                v00 = 0.5f*v00*(1.0f + erff(v00*0.70710678118654752f));
                v01 = 0.5f*v01*(1.0f + erff(v01*0.70710678118654752f));
                v10 = 0.5f*v10*(1.0f + erff(v10*0.70710678118654752f));
                v11 = 0.5f*v11*(1.0f + erff(v11*0.70710678118654752f));
            }
            float2 w0; w0.x = v00; w0.y = v01;
            float2 w1; w1.x = v10; w1.y = v11;
            *(float2*)(C + o0) = w0;
            *(float2*)(C + o1) = w1;
        }
    }
}

/* ---------------- Attention v2: 2-row register blocking per warp ----------
   Each warp processes q-rows (i, i+8) together: every Ks/Vs LDS feeds two
   accumulators. Per-row FMA order identical to v1 => bit-exact.            */
#define QKV_PAD 65
#define QKV_SZ  (Nx*QKV_PAD)
#define SMEM_ATTN_FLOATS (3*QKV_SZ + 8*400)
__global__ __launch_bounds__(256) void attn_kernel(const float* __restrict__ qkv,
                                                   float* __restrict__ out,
                                                   float* __restrict__ clsh)
{
    extern __shared__ float sm[];
    float* Qs = sm;
    float* Ks = sm + QKV_SZ;
    float* Vs = sm + 2*QKV_SZ;
    float* Pb = sm + 3*QKV_SZ;
    int h = blockIdx.x, b = blockIdx.y;
    int tid = threadIdx.x, warp = tid>>5, lane = tid&31;

    const float* base = qkv + (size_t)b*Nx*2304 + h*64;
    for (int i = tid; i < Nx*64; i += 256){
        int n = i>>6, c = i&63;
        size_t s = (size_t)n*2304 + c;
        Qs[n*QKV_PAD+c] = base[s];
        Ks[n*QKV_PAD+c] = base[s+768];
        Vs[n*QKV_PAD+c] = base[s+1536];
    }
    __syncthreads();

    float* pb0 = Pb + warp*400;
    float* pb1 = pb0 + 200;
    for (int i = warp; i < Nx; i += 16){
        int i1 = i + 8;
        bool has2 = (i1 < Nx);
        const float* qr0 = Qs + i*QKV_PAD;
        const float* qr1 = Qs + (has2 ? i1 : i)*QKV_PAD;
        float s0[7], s1[7];
        int joff[7];
        #pragma unroll
        for (int t=0;t<7;t++){
            s0[t]=0.f; s1[t]=0.f;
            int j=lane+32*t; joff[t] = (j<Nx ? j : 0)*QKV_PAD;
        }
        #pragma unroll 4
        for (int c=0;c<64;c++){
            float q0 = qr0[c], q1 = qr1[c];
            #pragma unroll
            for (int t=0;t<7;t++){
                float kv = Ks[joff[t]+c];
                s0[t] = fmaf(q0, kv, s0[t]);
                s1[t] = fmaf(q1, kv, s1[t]);
            }
        }
        /* softmax row 0 */
        {
            float mx = -3.0e38f;
            #pragma unroll
            for (int t=0;t<7;t++){
                int j=lane+32*t;
                s0[t] = (j<Nx) ? s0[t]*0.125f : -3.0e38f;
                mx = fmaxf(mx, s0[t]);
            }
            #pragma unroll
            for (int o=16;o;o>>=1) mx = fmaxf(mx, __shfl_xor_sync(0xffffffffu, mx, o));
            float sum = 0.f;
            #pragma unroll
            for (int t=0;t<7;t++){
                int j=lane+32*t;
                float e = (j<Nx) ? expf(s0[t]-mx) : 0.f;
                s0[t]=e; sum+=e;
            }
            #pragma unroll
            for (int o=16;o;o>>=1) sum += __shfl_xor_sync(0xffffffffu, sum, o);
            float inv = 1.0f/sum;
            #pragma unroll
            for (int t=0;t<7;t++){
                int j=lane+32*t;
                if (j<Nx) pb0[j] = s0[t]*inv;
            }
            if (i == 0){
                #pragma unroll
                for (int t=0;t<7;t++){
                    int j=lane+32*t;
                    if (j>=1 && j<Nx) clsh[((size_t)b*Hx + h)*196 + (j-1)] = s0[t]*inv;
                }
            }
        }
        /* softmax row 1 */
        if (has2){
            float mx = -3.0e38f;
            #pragma unroll
            for (int t=0;t<7;t++){
                int j=lane+32*t;
                s1[t] = (j<Nx) ? s1[t]*0.125f : -3.0e38f;
                mx = fmaxf(mx, s1[t]);
            }
            #pragma unroll
            for (int o=16;o;o>>=1) mx = fmaxf(mx, __shfl_xor_sync(0xffffffffu, mx, o));
            float sum = 0.f;
            #pragma unroll
            for (int t=0;t<7;t++){
                int j=lane+32*t;
                float e = (j<Nx) ? expf(s1[t]-mx) : 0.f;
                s1[t]=e; sum+=e;
            }
            #pragma unroll
            for (int o=16;o;o>>=1) sum += __shfl_xor_sync(0xffffffffu, sum, o);
            float inv = 1.0f/sum;
            #pragma unroll
            for (int t=0;t<7;t++){
                int j=lane+32*t;
                if (j<Nx) pb1[j] = s1[t]*inv;
            }
        }
        __syncwarp();
        /* AV: each Vs LDS feeds both rows */
        float o0a=0.f, o1a=0.f, o0b=0.f, o1b=0.f;
        for (int j=0;j<Nx;j++){
            float v0 = Vs[j*QKV_PAD+lane];
            float v1 = Vs[j*QKV_PAD+lane+32];
            float p0 = pb0[j];
            o0a = fmaf(p0, v0, o0a);
            o1a = fmaf(p0, v1, o1a);
            float p1 = pb1[j];
            o0b = fmaf(p1, v0, o0b);
            o1b = fmaf(p1, v1, o1b);
        }
        size_t oo = (size_t)(b*Nx + i)*Cx + h*64;
        out[oo + lane]      = o0a;
        out[oo + lane + 32] = o1a;
        if (has2){
            size_t oo1 = (size_t)(b*Nx + i1)*Cx + h*64;
            out[oo1 + lane]      = o0b;
            out[oo1 + lane + 32] = o1b;
        }
        __syncwarp();
    }
}

/* ---------------- cls_attn = mean over heads ---------------- */
__global__ void cls_mean_kernel()
{
    int b = blockIdx.x, j = threadIdx.x;
    if (j < 196){
        float s = 0.f;
        #pragma unroll
        for (int h=0; h<Hx; h++) s += g_clsh[((size_t)b*Hx + h)*196 + j];
        g_cls[b*196 + j] = s * (1.0f/12.0f);
    }
}

/* ---------------- top-k via bitonic sort + complement ---------------- */
__global__ __launch_bounds__(256) void topk_kernel()
{
    __shared__ float v[256];
    __shared__ int   id[256];
    __shared__ unsigned char sel[196];
    int b = blockIdx.x, t = threadIdx.x;
    v[t]  = (t < 196) ? g_cls[b*196 + t] : -3.0e38f;
    id[t] = t;
    __syncthreads();
    for (int k=2;k<=256;k<<=1){
        for (int j=k>>1;j>0;j>>=1){
            int ixj = t ^ j;
            if (ixj > t){
                float va=v[t], vb=v[ixj];
                int   ia=id[t], ib=id[ixj];
                bool aWorse = (va < vb) || (va == vb && ia > ib);
                bool dirDesc = ((t & k) == 0);
                bool doswap = dirDesc ? aWorse : !aWorse;
                if (doswap){ v[t]=vb; v[ixj]=va; id[t]=ib; id[ixj]=ia; }
            }
            __syncthreads();
        }
    }
    if (t < LEFT) g_idx[b*LEFT + t] = id[t];
    if (t < 196) sel[t] = 0;
    __syncthreads();
    if (t < LEFT) sel[id[t]] = 1;
    __syncthreads();
    if (t == 0){
        int c = 0;
        for (int j=0;j<196;j++) if (!sel[j]) g_cmp[b*CMPL + (c++)] = j;
    }
}

/* ---------------- gathers ---------------- */
__global__ __launch_bounds__(256) void gather_xo_kernel()
{
    int l = blockIdx.x, b = blockIdx.y, t = threadIdx.x;
    float* dst = g_XO + ((size_t)b*144 + l)*Cx;
    float ss = 0.f;
    if (l < LEFT){
        int j = g_idx[b*LEFT + l];
        const float* src = g_x1 + ((size_t)(b*Nx) + 1 + j)*Cx;
        #pragma unroll
        for (int r=0;r<3;r++){
            float vv = src[t + r*256];
            dst[t + r*256] = vv;
            ss += vv*vv;
        }
    } else {
        #pragma unroll
        for (int r=0;r<3;r++) dst[t + r*256] = 0.f;
    }
    __shared__ float sr[8];
    #pragma unroll
    for (int o=16;o;o>>=1) ss += __shfl_xor_sync(0xffffffffu, ss, o);
    if ((t&31)==0) sr[t>>5] = ss;
    __syncthreads();
    if (t == 0 && l < LEFT){
        float tot = 0.f;
        #pragma unroll
        for (int i=0;i<8;i++) tot += sr[i];
        g_nrm[b*LEFT + l] = sqrtf(tot);
    }
}

__global__ __launch_bounds__(256) void gather_nt_kernel()
{
    int m = blockIdx.x, b = blockIdx.y, t = threadIdx.x;
    float* dst = g_NT + ((size_t)b*64 + m)*Cx;
    if (m < CMPL){
        int j = g_cmp[b*CMPL + m];
        const float* src = g_x1 + ((size_t)(b*Nx) + 1 + j)*Cx;
        #pragma unroll
        for (int r=0;r<3;r++) dst[t + r*256] = src[t + r*256];
    } else {
        #pragma unroll
        for (int r=0;r<3;r++) dst[t + r*256] = 0.f;
    }
}

/* ---------------- distance GEMM ---------------- */
__global__ __launch_bounds__(256) void dist_kernel()
{
    __shared__ float NTs[64*33];
    __shared__ float XOs[144*33];
    int b = blockIdx.x, tid = threadIdx.x;
    int tx = tid & 15, ty = tid >> 4;
    const float* NTb = g_NT + (size_t)b*64*Cx;
    const float* XOb = g_XO + (size_t)b*144*Cx;
    float acc[4][9];
    #pragma unroll
    for (int i=0;i<4;i++)
        #pragma unroll
        for (int j=0;j<9;j++) acc[i][j]=0.f;

    for (int k0=0;k0<Cx;k0+=32){
        for (int i=tid;i<64*32;i+=256){ int m=i>>5, kk=i&31; NTs[m*33+kk]=NTb[(size_t)m*Cx+k0+kk]; }
        for (int i=tid;i<144*32;i+=256){ int l=i>>5, kk=i&31; XOs[l*33+kk]=XOb[(size_t)l*Cx+k0+kk]; }
        __syncthreads();
        #pragma unroll 8
        for (int kk=0;kk<32;kk++){
            float a[4], bb2[9];
            #pragma unroll
            for (int ii=0;ii<4;ii++) a[ii]  = NTs[(ty*4+ii)*33 + kk];
            #pragma unroll
            for (int jj=0;jj<9;jj++) bb2[jj]= XOs[(tx*9+jj)*33 + kk];
            #pragma unroll
            for (int ii=0;ii<4;ii++)
                #pragma unroll
                for (int jj=0;jj<9;jj++)
                    acc[ii][jj] = fmaf(a[ii], bb2[jj], acc[ii][jj]);
        }
        __syncthreads();
    }
    #pragma unroll
    for (int ii=0;ii<4;ii++)
        #pragma unroll
        for (int jj=0;jj<9;jj++)
            g_D[(size_t)b*9216 + (ty*4+ii)*144 + (tx*9+jj)] = acc[ii][jj];
}

/* ---------------- argmax ---------------- */
__global__ void argmax_kernel()
{
    int m = blockIdx.x, b = blockIdx.y, lane = threadIdx.x;
    const float* Dr = g_D + (size_t)b*9216 + m*144;
    float best = -3.0e38f; int bi = 1<<30;
    for (int l=lane; l<LEFT; l+=32){
        float v = Dr[l] / g_nrm[b*LEFT + l];
        if (v > best || (v == best && l < bi)){ best = v; bi = l; }
    }
    #pragma unroll
    for (int o=16;o;o>>=1){
        float v2 = __shfl_xor_sync(0xffffffffu, best, o);
        int   i2 = __shfl_xor_sync(0xffffffffu, bi,   o);
        if (v2 > best || (v2 == best && i2 < bi)){ best = v2; bi = i2; }
    }
    if (lane == 0) g_node[b*CMPL + m] = bi;
}

/* ---------------- deterministic merge ---------------- */
__global__ __launch_bounds__(256) void merge_kernel()
{
    int l = blockIdx.x, b = blockIdx.y, t = threadIdx.x;
    int jt = g_idx[b*LEFT + l];
    float w = g_cls[b*196 + jt];
    const float* src = g_x1 + ((size_t)(b*Nx) + 1 + jt)*Cx;
    float a0 = src[t]*w, a1 = src[t+256]*w, a2 = src[t+512]*w;
    float tka = w;
    for (int m=0;m<CMPL;m++){
        if (g_node[b*CMPL + m] == l){
            int jm = g_cmp[b*CMPL + m];
            float wm = g_cls[b*196 + jm];
            const float* s2 = g_x1 + ((size_t)(b*Nx) + 1 + jm)*Cx;
            a0 += s2[t]*wm; a1 += s2[t+256]*wm; a2 += s2[t+512]*wm;
            tka += wm;
        }
    }
    float* dst = g_xm + ((size_t)(b*NM) + 1 + l)*Cx;
    dst[t]     = a0 / tka;
    dst[t+256] = a1 / tka;
    dst[t+512] = a2 / tka;
}

__global__ void copy_cls_kernel()
{
    int b = blockIdx.x, t = threadIdx.x;
    const float* s = g_x1 + (size_t)b*Nx*Cx;
    float* d = g_xm + (size_t)b*NM*Cx;
    #pragma unroll
    for (int r=0;r<3;r++) d[t + r*256] = s[t + r*256];
}

/* ---------------- host launcher ---------------- */
extern "C" void kernel_launch(void* const* d_in, const int* in_sizes, int n_in,
                              void* d_out, int out_size)
{
    const float* x     = (const float*)d_in[0];
    const float* n1w   = (const float*)d_in[1];
    const float* n1b   = (const float*)d_in[2];
    const float* qkvw  = (const float*)d_in[3];
    const float* projw = (const float*)d_in[4];
    const float* projb = (const float*)d_in[5];
    const float* n2w   = (const float*)d_in[6];
    const float* n2b   = (const float*)d_in[7];
    const float* fc1w  = (const float*)d_in[8];
    const float* fc1b  = (const float*)d_in[9];
    const float* fc2w  = (const float*)d_in[10];
    const float* fc2b  = (const float*)d_in[11];
    float* out = (float*)d_out;

    void *p;
    cudaGetSymbolAddress(&p, g_xn);   float* pxn  = (float*)p;
    cudaGetSymbolAddress(&p, g_qkv);  float* pqkv = (float*)p;
    cudaGetSymbolAddress(&p, g_ao);   float* pao  = (float*)p;
    cudaGetSymbolAddress(&p, g_x1);   float* px1  = (float*)p;
    cudaGetSymbolAddress(&p, g_clsh); float* pclsh= (float*)p;
    cudaGetSymbolAddress(&p, g_xm);   float* pxm  = (float*)p;
    cudaGetSymbolAddress(&p, g_xn2);  float* pxn2 = (float*)p;
    cudaGetSymbolAddress(&p, g_h1);   float* ph1  = (float*)p;

    /* 1) LN1 */
    ln_kernel<<<NROWS, 256>>>(x, n1w, n1b, pxn);

    /* 2) QKV GEMM (fp32 — feeds top-k selection) */
    sgemm<0><<<dim3(2304/128, NROWS/128), 256>>>(pxn, qkvw, nullptr, nullptr, pqkv,
                                                 NROWS, 2304, Cx);

    /* 3) attention (2-row blocked, bit-exact) */
    cudaFuncSetAttribute(attn_kernel, cudaFuncAttributeMaxDynamicSharedMemorySize,
                         SMEM_ATTN_FLOATS*4);
    attn_kernel<<<dim3(Hx, Bx), 256, SMEM_ATTN_FLOATS*4>>>(pqkv, pao, pclsh);

    /* 4) proj GEMM + bias + residual (fp32 — feeds argmax selection) */
    sgemm<2><<<dim3(Cx/128, NROWS/128), 256>>>(pao, projw, projb, x, px1,
                                               NROWS, Cx, Cx);

    /* 5-6) cls mean, top-k + complement */
    cls_mean_kernel<<<Bx, 256>>>();
    topk_kernel<<<Bx, 256>>>();

    /* 7-9) gathers, distance GEMM, argmax */
    gather_xo_kernel<<<dim3(144, Bx), 256>>>();
    gather_nt_kernel<<<dim3(64, Bx), 256>>>();
    dist_kernel<<<Bx, 256>>>();
    argmax_kernel<<<dim3(CMPL, Bx), 32>>>();

    /* 10) merge + cls copy */
    merge_kernel<<<dim3(LEFT, Bx), 256>>>();
    copy_cls_kernel<<<Bx, 256>>>();

    /* 11) LN2, 12) fc1+GELU (tf32 mma), 13) fc2+bias+residual (tf32 mma) */
    ln_kernel<<<M2, 256>>>(pxm, n2w, n2b, pxn2);
    mma_gemm<3><<<dim3(FF/128, M2/128), 256>>>(pxn2, fc1w, fc1b, nullptr, ph1,
                                               M2, FF, Cx);
    mma_gemm<2><<<dim3(Cx/128, M2/128), 256>>>(ph1, fc2w, fc2b, pxm, out,
                                               M2, Cx, FF);
    (void)in_sizes; (void)n_in; (void)out_size;
}